// round 1
// baseline (speedup 1.0000x reference)
#include <cuda_runtime.h>
#include <math.h>

typedef unsigned long long ull;

#define NM    16384
#define NSd   512
#define NIN   64
#define NOUT  64
#define BM    128
#define BN    64
#define BK    16
#define NTHREADS 256
#define TILES_M   (NM / BM)        // 128
#define TILES_NS  (NSd / BN)       // 8
#define NTILES    (TILES_M * TILES_NS)  // 1024
#define MAXITER   200
#define EPS_STOP  1e-3f

// ---------------- device scratch (no allocations allowed) ----------------
__device__ float g_xA[NM * NSd];          // x@A^T + b, 32 MB
__device__ float g_zb[2][NM * NSd];       // ping-pong z buffers (one reused for g)
__device__ unsigned g_barrier;
__device__ int g_zparity;                 // parity of buffer holding z_star
__device__ float g_part[2][2 * 1024];     // per-block residual partials, dbl-buffered
__device__ float g_jacpart[NTILES];       // per-tile sum(vJ^2) partials

// ---------------- packed f32x2 helpers ----------------
__device__ __forceinline__ ull pack2(float x) {
    ull r; unsigned u = __float_as_uint(x);
    asm("mov.b64 %0, {%1, %1};" : "=l"(r) : "r"(u));
    return r;
}
__device__ __forceinline__ void fma2(ull& d, ull a, ull b) {
    asm("fma.rn.f32x2 %0, %1, %2, %0;" : "+l"(d) : "l"(a), "l"(b));
}
__device__ __forceinline__ float2 unpack2(ull p) {
    unsigned lo, hi;
    asm("mov.b64 {%0, %1}, %2;" : "=r"(lo), "=r"(hi) : "l"(p));
    return make_float2(__uint_as_float(lo), __uint_as_float(hi));
}

// ---------------- grid-wide barrier (all CTAs resident: grid == #SMs) ----------------
__device__ __forceinline__ void grid_sync(unsigned expected) {
    __syncthreads();
    if (threadIdx.x == 0) {
        __threadfence();
        unsigned arr = atomicAdd(&g_barrier, 1u) + 1u;
        if (arr < expected) {
            while (*(volatile unsigned*)&g_barrier < expected) { }
        }
        __threadfence();
    }
    __syncthreads();
}

// ---------------- shared GEMM tile: C_tile(128x64) += A[m0:,:K] * Bop ----------------
// A row-major, stride lda. BTRANS: Bop(k,j) = B[(n0+j)*ldb + k]  (i.e. C = A @ B^T)
//                         else:   Bop(k,j) = B[k*ldb + n0 + j]   (i.e. C = A @ B)
// ACG: load A via __ldcg (needed for same-launch cross-SM coherence).
template<bool BTRANS, bool ACG>
__device__ __forceinline__ void gemm_tile(
    const float* __restrict__ Ag, int lda,
    const float* __restrict__ Bg, int ldb,
    int m0, int n0, int K,
    ull acc[8][2], float* sA, float* sB)
{
    const int tid = threadIdx.x;
    const int r0  = (tid >> 4) * 8;     // micro-tile row base (0..120)
    const int c0  = (tid & 15) * 4;     // micro-tile col base (0..60)
    const int lr  = tid >> 2;           // loader row   (0..63)
    const int lk4 = (tid & 3) * 4;      // loader k base (0,4,8,12)
    const int bk  = tid >> 4;           // !BTRANS loader k row (0..15)
    const int bj  = (tid & 15) * 4;     // !BTRANS loader col (0..60)
    const int NSTEP = K >> 4;

    const float* apr0 = Ag + (size_t)(m0 + lr) * lda;
    const float* apr1 = Ag + (size_t)(m0 + lr + 64) * lda;

    auto ldA = [&](const float* p) -> float4 {
        return ACG ? __ldcg((const float4*)p) : *(const float4*)p;
    };
    auto store_sm = [&](int b, float4 a0, float4 a1, float4 bb) {
        float* dA = sA + b * (BK * BM);
        dA[(lk4 + 0) * BM + lr] = a0.x;
        dA[(lk4 + 1) * BM + lr] = a0.y;
        dA[(lk4 + 2) * BM + lr] = a0.z;
        dA[(lk4 + 3) * BM + lr] = a0.w;
        dA[(lk4 + 0) * BM + lr + 64] = a1.x;
        dA[(lk4 + 1) * BM + lr + 64] = a1.y;
        dA[(lk4 + 2) * BM + lr + 64] = a1.z;
        dA[(lk4 + 3) * BM + lr + 64] = a1.w;
        float* dB = sB + b * (BK * BN);
        if (BTRANS) {
            dB[(lk4 + 0) * BN + lr] = bb.x;
            dB[(lk4 + 1) * BN + lr] = bb.y;
            dB[(lk4 + 2) * BN + lr] = bb.z;
            dB[(lk4 + 3) * BN + lr] = bb.w;
        } else {
            *(float4*)&dB[bk * BN + bj] = bb;
        }
    };

    float4 ra0, ra1, rb;
    ra0 = ldA(apr0 + lk4);
    ra1 = ldA(apr1 + lk4);
    if (BTRANS) rb = *(const float4*)(Bg + (size_t)(n0 + lr) * ldb + lk4);
    else        rb = *(const float4*)(Bg + (size_t)bk * ldb + n0 + bj);

    int buf = 0;
    store_sm(0, ra0, ra1, rb);
    __syncthreads();

    for (int s = 0; s < NSTEP; ++s) {
        float4 na0, na1, nb;
        if (s + 1 < NSTEP) {
            const int k0 = (s + 1) << 4;
            na0 = ldA(apr0 + k0 + lk4);
            na1 = ldA(apr1 + k0 + lk4);
            if (BTRANS) nb = *(const float4*)(Bg + (size_t)(n0 + lr) * ldb + k0 + lk4);
            else        nb = *(const float4*)(Bg + (size_t)(k0 + bk) * ldb + n0 + bj);
        }
        const float* cA = sA + buf * (BK * BM) + r0;
        const float* cB = sB + buf * (BK * BN) + c0;
#pragma unroll
        for (int k = 0; k < BK; ++k) {
            float4 a0 = *(const float4*)(cA + k * BM);
            float4 a1 = *(const float4*)(cA + k * BM + 4);
            ull b0 = *(const ull*)(cB + k * BN);
            ull b1 = *(const ull*)(cB + k * BN + 2);
            ull p;
            p = pack2(a0.x); fma2(acc[0][0], p, b0); fma2(acc[0][1], p, b1);
            p = pack2(a0.y); fma2(acc[1][0], p, b0); fma2(acc[1][1], p, b1);
            p = pack2(a0.z); fma2(acc[2][0], p, b0); fma2(acc[2][1], p, b1);
            p = pack2(a0.w); fma2(acc[3][0], p, b0); fma2(acc[3][1], p, b1);
            p = pack2(a1.x); fma2(acc[4][0], p, b0); fma2(acc[4][1], p, b1);
            p = pack2(a1.y); fma2(acc[5][0], p, b0); fma2(acc[5][1], p, b1);
            p = pack2(a1.z); fma2(acc[6][0], p, b0); fma2(acc[6][1], p, b1);
            p = pack2(a1.w); fma2(acc[7][0], p, b0); fma2(acc[7][1], p, b1);
        }
        if (s + 1 < NSTEP) {
            store_sm(buf ^ 1, na0, na1, nb);
            __syncthreads();
            buf ^= 1;
        }
    }
    __syncthreads();   // safe smem reuse by the caller / next tile
}

__device__ __forceinline__ float block_reduce(float v, float* sred) {
    const int tid = threadIdx.x;
    sred[tid] = v; __syncthreads();
#pragma unroll
    for (int o = 128; o > 0; o >>= 1) {
        if (tid < o) sred[tid] += sred[tid + o];
        __syncthreads();
    }
    float r = sred[0];
    __syncthreads();
    return r;
}

// ---------------- kernels ----------------
__global__ void k_init() { g_barrier = 0u; }

// xA = x @ A^T + b
__global__ void __launch_bounds__(NTHREADS) k_xA(const float* __restrict__ x,
                                                 const float* __restrict__ A,
                                                 const float* __restrict__ b) {
    __shared__ float sA[2 * BK * BM];
    __shared__ float sB[2 * BK * BN];
    const int bid = blockIdx.x;
    const int m0 = (bid / TILES_NS) * BM;
    const int n0 = (bid % TILES_NS) * BN;
    ull acc[8][2];
#pragma unroll
    for (int i = 0; i < 8; ++i) { acc[i][0] = 0ull; acc[i][1] = 0ull; }
    gemm_tile<true, false>(x, NIN, A, NIN, m0, n0, NIN, acc, sA, sB);

    const int tid = threadIdx.x;
    const int r0 = (tid >> 4) * 8, c0 = (tid & 15) * 4;
    const float b0 = b[n0 + c0], b1 = b[n0 + c0 + 1], b2 = b[n0 + c0 + 2], b3 = b[n0 + c0 + 3];
#pragma unroll
    for (int r = 0; r < 8; ++r) {
        float2 lo = unpack2(acc[r][0]), hi = unpack2(acc[r][1]);
        float4 o = make_float4(lo.x + b0, lo.y + b1, hi.x + b2, hi.y + b3);
        *(float4*)&g_xA[(size_t)(m0 + r0 + r) * NSd + n0 + c0] = o;
    }
}

// Persistent DEQ solver: z_{t} = tanh(xA + z_{t-1} @ Bm^T) with reference stopping
// rule, then g = v * (1 - tanh(xA + z* @ Bm^T)^2) into the other buffer.
__global__ void __launch_bounds__(NTHREADS) k_iter(const float* __restrict__ Bm,
                                                   const float* __restrict__ v) {
    __shared__ float sA[2 * BK * BM];
    __shared__ float sB[2 * BK * BN];
    __shared__ float sred[NTHREADS];
    __shared__ int   sdec[1];
    const int tid = threadIdx.x;
    const int nblk = gridDim.x;
    const int r0 = (tid >> 4) * 8, c0 = (tid & 15) * 4;
    unsigned bar_exp = 0;
    int final_p = 0;

    for (int t = 1; t <= MAXITER; ++t) {
        const float* zin = g_zb[t & 1];          // in(t)  (unused, uninit when t==1)
        float* zout = g_zb[(t - 1) & 1];         // out(t)
        float lnum = 0.f, lden = 0.f;

        for (int tile = blockIdx.x; tile < NTILES; tile += nblk) {
            const int m0 = (tile / TILES_NS) * BM;
            const int n0 = (tile % TILES_NS) * BN;
            ull acc[8][2];
#pragma unroll
            for (int i = 0; i < 8; ++i) { acc[i][0] = 0ull; acc[i][1] = 0ull; }
            if (t > 1)
                gemm_tile<true, true>(zin, NSd, Bm, NSd, m0, n0, NSd, acc, sA, sB);
#pragma unroll
            for (int r = 0; r < 8; ++r) {
                const size_t idx = (size_t)(m0 + r0 + r) * NSd + n0 + c0;
                float4 xa = *(const float4*)&g_xA[idx];
                float2 p0 = unpack2(acc[r][0]), p1 = unpack2(acc[r][1]);
                float4 c;
                c.x = tanhf(xa.x + p0.x);
                c.y = tanhf(xa.y + p0.y);
                c.z = tanhf(xa.z + p1.x);
                c.w = tanhf(xa.w + p1.y);
                if (t > 1) {
                    float4 zp = __ldcg((const float4*)&zin[idx]);
                    float dx = c.x - zp.x, dy = c.y - zp.y, dz = c.z - zp.z, dw = c.w - zp.w;
                    lnum += dx * dx + dy * dy + dz * dz + dw * dw;
                } else {
                    lnum += c.x * c.x + c.y * c.y + c.z * c.z + c.w * c.w;
                }
                lden += c.x * c.x + c.y * c.y + c.z * c.z + c.w * c.w;
                *(float4*)&zout[idx] = c;
            }
        }

        float bnum = block_reduce(lnum, sred);
        float bden = block_reduce(lden, sred);
        if (tid == 0) {
            const int slot = t & 1;
            g_part[slot][2 * blockIdx.x]     = bnum;
            g_part[slot][2 * blockIdx.x + 1] = bden;
        }
        bar_exp += nblk;
        grid_sync(bar_exp);

        if (tid == 0) {
            const int slot = t & 1;
            float num = 0.f, den = 0.f;
            for (int b2 = 0; b2 < nblk; ++b2) {
                num += __ldcg(&g_part[slot][2 * b2]);
                den += __ldcg(&g_part[slot][2 * b2 + 1]);
            }
            const float res = sqrtf(num) / (sqrtf(den) + 1e-8f);
            sdec[0] = (res <= EPS_STOP || t == MAXITER) ? 1 : 0;
        }
        __syncthreads();
        if (sdec[0]) { final_p = (t - 1) & 1; break; }
    }

    if (blockIdx.x == 0 && tid == 0) g_zparity = final_p;

    // g-phase: g = v * (1 - tanh(xA + z* @ Bm^T)^2)   (one more f-eval for the vjp)
    const float* zs = g_zb[final_p];
    float* gbuf = g_zb[final_p ^ 1];
    for (int tile = blockIdx.x; tile < NTILES; tile += gridDim.x) {
        const int m0 = (tile / TILES_NS) * BM;
        const int n0 = (tile % TILES_NS) * BN;
        ull acc[8][2];
#pragma unroll
        for (int i = 0; i < 8; ++i) { acc[i][0] = 0ull; acc[i][1] = 0ull; }
        gemm_tile<true, true>(zs, NSd, Bm, NSd, m0, n0, NSd, acc, sA, sB);
#pragma unroll
        for (int r = 0; r < 8; ++r) {
            const size_t idx = (size_t)(m0 + r0 + r) * NSd + n0 + c0;
            float4 xa = *(const float4*)&g_xA[idx];
            float4 vv = *(const float4*)&v[idx];
            float2 p0 = unpack2(acc[r][0]), p1 = unpack2(acc[r][1]);
            float4 o;
            float th;
            th = tanhf(xa.x + p0.x); o.x = vv.x * (1.f - th * th);
            th = tanhf(xa.y + p0.y); o.y = vv.y * (1.f - th * th);
            th = tanhf(xa.z + p1.x); o.z = vv.z * (1.f - th * th);
            th = tanhf(xa.w + p1.y); o.w = vv.w * (1.f - th * th);
            *(float4*)&gbuf[idx] = o;
        }
    }
}

// vJ = g @ Bm ; accumulate sum(vJ^2) per tile
__global__ void __launch_bounds__(NTHREADS) k_vjp(const float* __restrict__ Bm) {
    __shared__ float sA[2 * BK * BM];
    __shared__ float sB[2 * BK * BN];
    __shared__ float sred[NTHREADS];
    const int parity = g_zparity;
    const float* g = g_zb[parity ^ 1];
    const int bid = blockIdx.x;
    const int m0 = (bid / TILES_NS) * BM;
    const int n0 = (bid % TILES_NS) * BN;
    ull acc[8][2];
#pragma unroll
    for (int i = 0; i < 8; ++i) { acc[i][0] = 0ull; acc[i][1] = 0ull; }
    gemm_tile<false, false>(g, NSd, Bm, NSd, m0, n0, NSd, acc, sA, sB);
    float lsum = 0.f;
#pragma unroll
    for (int r = 0; r < 8; ++r) {
        float2 p0 = unpack2(acc[r][0]), p1 = unpack2(acc[r][1]);
        lsum += p0.x * p0.x + p0.y * p0.y + p1.x * p1.x + p1.y * p1.y;
    }
    float bsum = block_reduce(lsum, sred);
    if (threadIdx.x == 0) g_jacpart[bid] = bsum;
}

// y = z* @ Wh^T + bh  -> d_out[0 : NM*NOUT]
__global__ void __launch_bounds__(NTHREADS) k_y(const float* __restrict__ Wh,
                                                const float* __restrict__ bh,
                                                float* __restrict__ out) {
    __shared__ float sA[2 * BK * BM];
    __shared__ float sB[2 * BK * BN];
    const int parity = g_zparity;
    const float* zs = g_zb[parity];
    const int m0 = blockIdx.x * BM;
    ull acc[8][2];
#pragma unroll
    for (int i = 0; i < 8; ++i) { acc[i][0] = 0ull; acc[i][1] = 0ull; }
    gemm_tile<true, false>(zs, NSd, Wh, NSd, m0, 0, NSd, acc, sA, sB);
    const int tid = threadIdx.x;
    const int r0 = (tid >> 4) * 8, c0 = (tid & 15) * 4;
    const float b0 = bh[c0], b1 = bh[c0 + 1], b2 = bh[c0 + 2], b3 = bh[c0 + 3];
#pragma unroll
    for (int r = 0; r < 8; ++r) {
        float2 lo = unpack2(acc[r][0]), hi = unpack2(acc[r][1]);
        float4 o = make_float4(lo.x + b0, lo.y + b1, hi.x + b2, hi.y + b3);
        *(float4*)&out[(size_t)(m0 + r0 + r) * NOUT + c0] = o;
    }
}

// jac_loss = sum(g_jacpart) / (NM*NSd) -> d_out[NM*NOUT]
__global__ void k_jac(float* __restrict__ out) {
    __shared__ float sred[NTHREADS];
    const int tid = threadIdx.x;
    float s = 0.f;
    for (int i = tid; i < NTILES; i += NTHREADS) s += g_jacpart[i];
    sred[tid] = s; __syncthreads();
    for (int o = 128; o > 0; o >>= 1) {
        if (tid < o) sred[tid] += sred[tid + o];
        __syncthreads();
    }
    if (tid == 0) out[(size_t)NM * NOUT] = sred[0] / ((float)NM * (float)NSd);
}

// ---------------- launcher ----------------
extern "C" void kernel_launch(void* const* d_in, const int* in_sizes, int n_in,
                              void* d_out, int out_size) {
    const float* x   = (const float*)d_in[0];
    const float* A   = (const float*)d_in[1];
    const float* Bm  = (const float*)d_in[2];
    const float* b   = (const float*)d_in[3];
    const float* Wh  = (const float*)d_in[4];
    const float* bh  = (const float*)d_in[5];
    const float* v   = (const float*)d_in[6];
    float* out = (float*)d_out;

    static int nsm = 0;
    if (nsm == 0) {
        if (cudaDeviceGetAttribute(&nsm, cudaDevAttrMultiProcessorCount, 0) != cudaSuccess || nsm <= 0)
            nsm = 148;
        if (nsm > 1024) nsm = 1024;
    }

    k_init<<<1, 1>>>();
    k_xA<<<NTILES, NTHREADS>>>(x, A, b);
    k_iter<<<nsm, NTHREADS>>>(Bm, v);
    k_vjp<<<NTILES, NTHREADS>>>(Bm);
    k_y<<<TILES_M, NTHREADS>>>(Wh, bh, out);
    k_jac<<<1, NTHREADS>>>(out);
}

// round 2
// speedup vs baseline: 1.0026x; 1.0026x over previous
#include <cuda_runtime.h>
#include <math.h>

typedef unsigned long long ull;

#define NM    16384
#define NSd   512
#define NIN   64
#define NOUT  64
#define BM    128
#define BN    64
#define BK    16
#define NTHREADS 256
#define TILES_M   (NM / BM)        // 128
#define TILES_NS  (NSd / BN)       // 8
#define NTILES    (TILES_M * TILES_NS)  // 1024
#define MAXITER   200
#define EPS_STOP  1e-3f

// ---------------- device scratch (no allocations allowed) ----------------
__device__ float g_xA[NM * NSd];          // x@A^T + b, 32 MB
__device__ float g_zb[2][NM * NSd];       // ping-pong z buffers (one reused for g)
__device__ unsigned g_barrier;
__device__ int g_zparity;                 // parity of buffer holding z_star
__device__ float g_part[2][2 * 1024];     // per-block residual partials, dbl-buffered
__device__ float g_jacpart[NTILES];       // per-tile sum(vJ^2) partials

// ---------------- packed f32x2 helpers ----------------
__device__ __forceinline__ ull pack2(float x) {
    ull r; unsigned u = __float_as_uint(x);
    asm("mov.b64 %0, {%1, %1};" : "=l"(r) : "r"(u));
    return r;
}
__device__ __forceinline__ void fma2(ull& d, ull a, ull b) {
    asm("fma.rn.f32x2 %0, %1, %2, %0;" : "+l"(d) : "l"(a), "l"(b));
}
__device__ __forceinline__ float2 unpack2(ull p) {
    unsigned lo, hi;
    asm("mov.b64 {%0, %1}, %2;" : "=r"(lo), "=r"(hi) : "l"(p));
    return make_float2(__uint_as_float(lo), __uint_as_float(hi));
}

// ---------------- grid-wide barrier (all CTAs resident: grid == #SMs) ----------------
__device__ __forceinline__ void grid_sync(unsigned expected) {
    __syncthreads();
    if (threadIdx.x == 0) {
        __threadfence();
        unsigned arr = atomicAdd(&g_barrier, 1u) + 1u;
        if (arr < expected) {
            while (*(volatile unsigned*)&g_barrier < expected) { }
        }
        __threadfence();
    }
    __syncthreads();
}

// ---------------- shared GEMM tile: C_tile(128x64) += A[m0:,:K] * Bop ----------------
// A row-major, stride lda. BTRANS: Bop(k,j) = B[(n0+j)*ldb + k]  (i.e. C = A @ B^T)
//                         else:   Bop(k,j) = B[k*ldb + n0 + j]   (i.e. C = A @ B)
// ACG: load A via __ldcg (needed for same-launch cross-SM coherence).
template<bool BTRANS, bool ACG>
__device__ __forceinline__ void gemm_tile(
    const float* __restrict__ Ag, int lda,
    const float* __restrict__ Bg, int ldb,
    int m0, int n0, int K,
    ull acc[8][2], float* sA, float* sB)
{
    const int tid = threadIdx.x;
    const int r0  = (tid >> 4) * 8;     // micro-tile row base (0..120)
    const int c0  = (tid & 15) * 4;     // micro-tile col base (0..60)
    const int lr  = tid >> 2;           // loader row   (0..63)
    const int lk4 = (tid & 3) * 4;      // loader k base (0,4,8,12)
    const int bk  = tid >> 4;           // !BTRANS loader k row (0..15)
    const int bj  = (tid & 15) * 4;     // !BTRANS loader col (0..60)
    const int NSTEP = K >> 4;

    const float* apr0 = Ag + (size_t)(m0 + lr) * lda;
    const float* apr1 = Ag + (size_t)(m0 + lr + 64) * lda;

    auto ldA = [&](const float* p) -> float4 {
        return ACG ? __ldcg((const float4*)p) : *(const float4*)p;
    };
    auto store_sm = [&](int b, float4 a0, float4 a1, float4 bb) {
        float* dA = sA + b * (BK * BM);
        dA[(lk4 + 0) * BM + lr] = a0.x;
        dA[(lk4 + 1) * BM + lr] = a0.y;
        dA[(lk4 + 2) * BM + lr] = a0.z;
        dA[(lk4 + 3) * BM + lr] = a0.w;
        dA[(lk4 + 0) * BM + lr + 64] = a1.x;
        dA[(lk4 + 1) * BM + lr + 64] = a1.y;
        dA[(lk4 + 2) * BM + lr + 64] = a1.z;
        dA[(lk4 + 3) * BM + lr + 64] = a1.w;
        float* dB = sB + b * (BK * BN);
        if (BTRANS) {
            dB[(lk4 + 0) * BN + lr] = bb.x;
            dB[(lk4 + 1) * BN + lr] = bb.y;
            dB[(lk4 + 2) * BN + lr] = bb.z;
            dB[(lk4 + 3) * BN + lr] = bb.w;
        } else {
            *(float4*)&dB[bk * BN + bj] = bb;
        }
    };

    float4 ra0, ra1, rb;
    ra0 = ldA(apr0 + lk4);
    ra1 = ldA(apr1 + lk4);
    if (BTRANS) rb = *(const float4*)(Bg + (size_t)(n0 + lr) * ldb + lk4);
    else        rb = *(const float4*)(Bg + (size_t)bk * ldb + n0 + bj);

    int buf = 0;
    store_sm(0, ra0, ra1, rb);
    __syncthreads();

    for (int s = 0; s < NSTEP; ++s) {
        float4 na0, na1, nb;
        if (s + 1 < NSTEP) {
            const int k0 = (s + 1) << 4;
            na0 = ldA(apr0 + k0 + lk4);
            na1 = ldA(apr1 + k0 + lk4);
            if (BTRANS) nb = *(const float4*)(Bg + (size_t)(n0 + lr) * ldb + k0 + lk4);
            else        nb = *(const float4*)(Bg + (size_t)(k0 + bk) * ldb + n0 + bj);
        }
        const float* cA = sA + buf * (BK * BM) + r0;
        const float* cB = sB + buf * (BK * BN) + c0;
#pragma unroll
        for (int k = 0; k < BK; ++k) {
            float4 a0 = *(const float4*)(cA + k * BM);
            float4 a1 = *(const float4*)(cA + k * BM + 4);
            ull b0 = *(const ull*)(cB + k * BN);
            ull b1 = *(const ull*)(cB + k * BN + 2);
            ull p;
            p = pack2(a0.x); fma2(acc[0][0], p, b0); fma2(acc[0][1], p, b1);
            p = pack2(a0.y); fma2(acc[1][0], p, b0); fma2(acc[1][1], p, b1);
            p = pack2(a0.z); fma2(acc[2][0], p, b0); fma2(acc[2][1], p, b1);
            p = pack2(a0.w); fma2(acc[3][0], p, b0); fma2(acc[3][1], p, b1);
            p = pack2(a1.x); fma2(acc[4][0], p, b0); fma2(acc[4][1], p, b1);
            p = pack2(a1.y); fma2(acc[5][0], p, b0); fma2(acc[5][1], p, b1);
            p = pack2(a1.z); fma2(acc[6][0], p, b0); fma2(acc[6][1], p, b1);
            p = pack2(a1.w); fma2(acc[7][0], p, b0); fma2(acc[7][1], p, b1);
        }
        if (s + 1 < NSTEP) {
            store_sm(buf ^ 1, na0, na1, nb);
            __syncthreads();
            buf ^= 1;
        }
    }
    __syncthreads();   // safe smem reuse by the caller / next tile
}

__device__ __forceinline__ float block_reduce(float v, float* sred) {
    const int tid = threadIdx.x;
    sred[tid] = v; __syncthreads();
#pragma unroll
    for (int o = 128; o > 0; o >>= 1) {
        if (tid < o) sred[tid] += sred[tid + o];
        __syncthreads();
    }
    float r = sred[0];
    __syncthreads();
    return r;
}

// ---------------- kernels ----------------
__global__ void k_init() { g_barrier = 0u; }

// xA = x @ A^T + b
__global__ void __launch_bounds__(NTHREADS) k_xA(const float* __restrict__ x,
                                                 const float* __restrict__ A,
                                                 const float* __restrict__ b) {
    __shared__ float sA[2 * BK * BM];
    __shared__ float sB[2 * BK * BN];
    const int bid = blockIdx.x;
    const int m0 = (bid / TILES_NS) * BM;
    const int n0 = (bid % TILES_NS) * BN;
    ull acc[8][2];
#pragma unroll
    for (int i = 0; i < 8; ++i) { acc[i][0] = 0ull; acc[i][1] = 0ull; }
    gemm_tile<true, false>(x, NIN, A, NIN, m0, n0, NIN, acc, sA, sB);

    const int tid = threadIdx.x;
    const int r0 = (tid >> 4) * 8, c0 = (tid & 15) * 4;
    const float b0 = b[n0 + c0], b1 = b[n0 + c0 + 1], b2 = b[n0 + c0 + 2], b3 = b[n0 + c0 + 3];
#pragma unroll
    for (int r = 0; r < 8; ++r) {
        float2 lo = unpack2(acc[r][0]), hi = unpack2(acc[r][1]);
        float4 o = make_float4(lo.x + b0, lo.y + b1, hi.x + b2, hi.y + b3);
        *(float4*)&g_xA[(size_t)(m0 + r0 + r) * NSd + n0 + c0] = o;
    }
}

// Persistent DEQ solver: z_{t} = tanh(xA + z_{t-1} @ Bm^T) with reference stopping
// rule, then g = v * (1 - tanh(xA + z* @ Bm^T)^2) into the other buffer.
__global__ void __launch_bounds__(NTHREADS) k_iter(const float* __restrict__ Bm,
                                                   const float* __restrict__ v) {
    __shared__ float sA[2 * BK * BM];
    __shared__ float sB[2 * BK * BN];
    __shared__ float sred[NTHREADS];
    __shared__ int   sdec[1];
    const int tid = threadIdx.x;
    const int nblk = gridDim.x;
    const int r0 = (tid >> 4) * 8, c0 = (tid & 15) * 4;
    unsigned bar_exp = 0;
    int final_p = 0;

    for (int t = 1; t <= MAXITER; ++t) {
        const float* zin = g_zb[t & 1];          // in(t)  (unused, uninit when t==1)
        float* zout = g_zb[(t - 1) & 1];         // out(t)
        float lnum = 0.f, lden = 0.f;

        for (int tile = blockIdx.x; tile < NTILES; tile += nblk) {
            const int m0 = (tile / TILES_NS) * BM;
            const int n0 = (tile % TILES_NS) * BN;
            ull acc[8][2];
#pragma unroll
            for (int i = 0; i < 8; ++i) { acc[i][0] = 0ull; acc[i][1] = 0ull; }
            if (t > 1)
                gemm_tile<true, true>(zin, NSd, Bm, NSd, m0, n0, NSd, acc, sA, sB);
#pragma unroll
            for (int r = 0; r < 8; ++r) {
                const size_t idx = (size_t)(m0 + r0 + r) * NSd + n0 + c0;
                float4 xa = *(const float4*)&g_xA[idx];
                float2 p0 = unpack2(acc[r][0]), p1 = unpack2(acc[r][1]);
                float4 c;
                c.x = tanhf(xa.x + p0.x);
                c.y = tanhf(xa.y + p0.y);
                c.z = tanhf(xa.z + p1.x);
                c.w = tanhf(xa.w + p1.y);
                if (t > 1) {
                    float4 zp = __ldcg((const float4*)&zin[idx]);
                    float dx = c.x - zp.x, dy = c.y - zp.y, dz = c.z - zp.z, dw = c.w - zp.w;
                    lnum += dx * dx + dy * dy + dz * dz + dw * dw;
                } else {
                    lnum += c.x * c.x + c.y * c.y + c.z * c.z + c.w * c.w;
                }
                lden += c.x * c.x + c.y * c.y + c.z * c.z + c.w * c.w;
                *(float4*)&zout[idx] = c;
            }
        }

        float bnum = block_reduce(lnum, sred);
        float bden = block_reduce(lden, sred);
        if (tid == 0) {
            const int slot = t & 1;
            g_part[slot][2 * blockIdx.x]     = bnum;
            g_part[slot][2 * blockIdx.x + 1] = bden;
        }
        bar_exp += nblk;
        grid_sync(bar_exp);

        if (tid == 0) {
            const int slot = t & 1;
            float num = 0.f, den = 0.f;
            for (int b2 = 0; b2 < nblk; ++b2) {
                num += __ldcg(&g_part[slot][2 * b2]);
                den += __ldcg(&g_part[slot][2 * b2 + 1]);
            }
            const float res = sqrtf(num) / (sqrtf(den) + 1e-8f);
            sdec[0] = (res <= EPS_STOP || t == MAXITER) ? 1 : 0;
        }
        __syncthreads();
        if (sdec[0]) { final_p = (t - 1) & 1; break; }
    }

    if (blockIdx.x == 0 && tid == 0) g_zparity = final_p;

    // g-phase: g = v * (1 - tanh(xA + z* @ Bm^T)^2)   (one more f-eval for the vjp)
    const float* zs = g_zb[final_p];
    float* gbuf = g_zb[final_p ^ 1];
    for (int tile = blockIdx.x; tile < NTILES; tile += gridDim.x) {
        const int m0 = (tile / TILES_NS) * BM;
        const int n0 = (tile % TILES_NS) * BN;
        ull acc[8][2];
#pragma unroll
        for (int i = 0; i < 8; ++i) { acc[i][0] = 0ull; acc[i][1] = 0ull; }
        gemm_tile<true, true>(zs, NSd, Bm, NSd, m0, n0, NSd, acc, sA, sB);
#pragma unroll
        for (int r = 0; r < 8; ++r) {
            const size_t idx = (size_t)(m0 + r0 + r) * NSd + n0 + c0;
            float4 xa = *(const float4*)&g_xA[idx];
            float4 vv = *(const float4*)&v[idx];
            float2 p0 = unpack2(acc[r][0]), p1 = unpack2(acc[r][1]);
            float4 o;
            float th;
            th = tanhf(xa.x + p0.x); o.x = vv.x * (1.f - th * th);
            th = tanhf(xa.y + p0.y); o.y = vv.y * (1.f - th * th);
            th = tanhf(xa.z + p1.x); o.z = vv.z * (1.f - th * th);
            th = tanhf(xa.w + p1.y); o.w = vv.w * (1.f - th * th);
            *(float4*)&gbuf[idx] = o;
        }
    }
}

// vJ = g @ Bm ; accumulate sum(vJ^2) per tile
__global__ void __launch_bounds__(NTHREADS) k_vjp(const float* __restrict__ Bm) {
    __shared__ float sA[2 * BK * BM];
    __shared__ float sB[2 * BK * BN];
    __shared__ float sred[NTHREADS];
    const int parity = g_zparity;
    const float* g = g_zb[parity ^ 1];
    const int bid = blockIdx.x;
    const int m0 = (bid / TILES_NS) * BM;
    const int n0 = (bid % TILES_NS) * BN;
    ull acc[8][2];
#pragma unroll
    for (int i = 0; i < 8; ++i) { acc[i][0] = 0ull; acc[i][1] = 0ull; }
    gemm_tile<false, false>(g, NSd, Bm, NSd, m0, n0, NSd, acc, sA, sB);
    float lsum = 0.f;
#pragma unroll
    for (int r = 0; r < 8; ++r) {
        float2 p0 = unpack2(acc[r][0]), p1 = unpack2(acc[r][1]);
        lsum += p0.x * p0.x + p0.y * p0.y + p1.x * p1.x + p1.y * p1.y;
    }
    float bsum = block_reduce(lsum, sred);
    if (threadIdx.x == 0) g_jacpart[bid] = bsum;
}

// y = z* @ Wh^T + bh  -> d_out[0 : NM*NOUT]
__global__ void __launch_bounds__(NTHREADS) k_y(const float* __restrict__ Wh,
                                                const float* __restrict__ bh,
                                                float* __restrict__ out) {
    __shared__ float sA[2 * BK * BM];
    __shared__ float sB[2 * BK * BN];
    const int parity = g_zparity;
    const float* zs = g_zb[parity];
    const int m0 = blockIdx.x * BM;
    ull acc[8][2];
#pragma unroll
    for (int i = 0; i < 8; ++i) { acc[i][0] = 0ull; acc[i][1] = 0ull; }
    gemm_tile<true, false>(zs, NSd, Wh, NSd, m0, 0, NSd, acc, sA, sB);
    const int tid = threadIdx.x;
    const int r0 = (tid >> 4) * 8, c0 = (tid & 15) * 4;
    const float b0 = bh[c0], b1 = bh[c0 + 1], b2 = bh[c0 + 2], b3 = bh[c0 + 3];
#pragma unroll
    for (int r = 0; r < 8; ++r) {
        float2 lo = unpack2(acc[r][0]), hi = unpack2(acc[r][1]);
        float4 o = make_float4(lo.x + b0, lo.y + b1, hi.x + b2, hi.y + b3);
        *(float4*)&out[(size_t)(m0 + r0 + r) * NOUT + c0] = o;
    }
}

// jac_loss = sum(g_jacpart) / (NM*NSd) -> d_out[NM*NOUT]
__global__ void k_jac(float* __restrict__ out) {
    __shared__ float sred[NTHREADS];
    const int tid = threadIdx.x;
    float s = 0.f;
    for (int i = tid; i < NTILES; i += NTHREADS) s += g_jacpart[i];
    sred[tid] = s; __syncthreads();
    for (int o = 128; o > 0; o >>= 1) {
        if (tid < o) sred[tid] += sred[tid + o];
        __syncthreads();
    }
    if (tid == 0) out[(size_t)NM * NOUT] = sred[0] / ((float)NM * (float)NSd);
}

// ---------------- launcher ----------------
extern "C" void kernel_launch(void* const* d_in, const int* in_sizes, int n_in,
                              void* d_out, int out_size) {
    const float* x   = (const float*)d_in[0];
    const float* A   = (const float*)d_in[1];
    const float* Bm  = (const float*)d_in[2];
    const float* b   = (const float*)d_in[3];
    const float* Wh  = (const float*)d_in[4];
    const float* bh  = (const float*)d_in[5];
    const float* v   = (const float*)d_in[6];
    float* out = (float*)d_out;

    static int nsm = 0;
    if (nsm == 0) {
        if (cudaDeviceGetAttribute(&nsm, cudaDevAttrMultiProcessorCount, 0) != cudaSuccess || nsm <= 0)
            nsm = 148;
        if (nsm > 1024) nsm = 1024;
    }

    k_init<<<1, 1>>>();
    k_xA<<<NTILES, NTHREADS>>>(x, A, b);
    k_iter<<<nsm, NTHREADS>>>(Bm, v);
    k_vjp<<<NTILES, NTHREADS>>>(Bm);
    k_y<<<TILES_M, NTHREADS>>>(Wh, bh, out);
    k_jac<<<1, NTHREADS>>>(out);
}

// round 5
// speedup vs baseline: 2.0693x; 2.0638x over previous
#include <cuda_runtime.h>
#include <math.h>
#include <stdint.h>

typedef unsigned long long ull;

#define NM    16384
#define NSd   512
#define NIN   64
#define NOUT  64
#define BM    128
#define BN    64
#define BK    16
#define NTHREADS 256
#define TILES_M   (NM / BM)            // 128
#define TILES_NS  (NSd / BN)           // 8
#define NTILES    (TILES_M * TILES_NS) // 1024
#define MAXITER   200
#define EPS_STOP  1e-3f

// ---- tensor (mma.sync tf32) path constants ----
#define GRID_IT   128                  // persistent CTAs, one M=128 tile each
#define KC        32                   // K per SMEM chunk
#define NCHUNK    16                   // 512 / 32
#define NPASS     4                    // N covered in 4 chunks of 128
#define LDW       36                   // padded smem row (floats) -> conflict-free frag LDS
#define TILEF     (128 * LDW)          // floats per staged tile (A or B)
#define STAGEF    (2 * TILEF)          // A + B per stage
#define SMEM_DYN  (2 * STAGEF * 4)     // double-buffered, bytes = 73728

// ---------------- device scratch ----------------
__device__ float g_xA[NM * NSd];          // x@A^T + b (exact fp32)
__device__ float g_zb[2][NM * NSd];       // ping-pong z buffers (one reused for g)
__device__ float g_BmR[NSd * NSd];        // tf32-rounded Bm
__device__ float g_BmT[NSd * NSd];        // tf32-rounded Bm^T
__device__ unsigned g_barrier;
__device__ int g_zparity;
__device__ float g_part[2][2 * GRID_IT];
__device__ float g_jacpart[GRID_IT];

// ---------------- small helpers ----------------
__device__ __forceinline__ uint32_t smem_u32(const void* p) {
    uint32_t a;
    asm("{ .reg .u64 t; cvta.to.shared.u64 t, %1; cvt.u32.u64 %0, t; }" : "=r"(a) : "l"(p));
    return a;
}
__device__ __forceinline__ float tf32r(float x) {
    uint32_t o;
    asm("cvt.rna.tf32.f32 %0, %1;" : "=r"(o) : "f"(x));
    return __uint_as_float(o);
}
__device__ __forceinline__ void cp_async16(uint32_t saddr, const float* g) {
    asm volatile("cp.async.cg.shared.global [%0], [%1], 16;" :: "r"(saddr), "l"(g) : "memory");
}
__device__ __forceinline__ void mma_tf32(float c[4], const float a[4], const float b[2]) {
    asm volatile(
        "mma.sync.aligned.m16n8k8.row.col.f32.tf32.tf32.f32 "
        "{%0,%1,%2,%3}, {%4,%5,%6,%7}, {%8,%9}, {%0,%1,%2,%3};"
        : "+f"(c[0]), "+f"(c[1]), "+f"(c[2]), "+f"(c[3])
        : "r"(__float_as_uint(a[0])), "r"(__float_as_uint(a[1])),
          "r"(__float_as_uint(a[2])), "r"(__float_as_uint(a[3])),
          "r"(__float_as_uint(b[0])), "r"(__float_as_uint(b[1])));
}

// ---------------- grid barrier (all CTAs resident: 128 <= #SMs) ----------------
__device__ __forceinline__ void grid_sync(unsigned expected) {
    __syncthreads();
    if (threadIdx.x == 0) {
        __threadfence();
        unsigned arr = atomicAdd(&g_barrier, 1u) + 1u;
        if (arr < expected) {
            while (*(volatile unsigned*)&g_barrier < expected) { }
        }
        __threadfence();
    }
    __syncthreads();
}

__device__ __forceinline__ float block_reduce(float v, float* sred) {
    const int tid = threadIdx.x;
    sred[tid] = v; __syncthreads();
#pragma unroll
    for (int o = 128; o > 0; o >>= 1) {
        if (tid < o) sred[tid] += sred[tid + o];
        __syncthreads();
    }
    float r = sred[0];
    __syncthreads();
    return r;
}

// ---------------- mma.sync tf32 pass: acc[128x128] = Arows(128x512) @ Brows(128x512)^T ----
// Arows: CTA's M-tile base, row stride 512 (rows m, cols k)
// Brows: operand rows = output n-dim (row n holds its 512 k-values)
// Warp layout: 8 warps = 2(M) x 4(N); warp tile 64x32; frag m16n8k8.
__device__ void mma_pass(const float* __restrict__ Arows,
                         const float* __restrict__ Brows,
                         float* __restrict__ sm, uint32_t smb,
                         float acc[4][4][4]) {
    const int tid = threadIdx.x;
    const int w = tid >> 5, lane = tid & 31;
    const int wr = w >> 2, wc = w & 3;
    const int grp = lane >> 2, tg = lane & 3;

#pragma unroll
    for (int f = 0; f < 4; ++f)
#pragma unroll
        for (int g = 0; g < 4; ++g)
#pragma unroll
            for (int r = 0; r < 4; ++r) acc[f][g][r] = 0.f;

    __syncthreads();   // previous users of smem done

    const int lrow = tid >> 3, lq = tid & 7;   // loader: 32 rows per i-step, 8 float4/row

    auto load_chunk = [&](int c) {
        const uint32_t sb = smb + (uint32_t)((c & 1) * STAGEF) * 4u;
        const int k0 = c * KC;
#pragma unroll
        for (int i = 0; i < 4; ++i) {
            const int row = i * 32 + lrow;
            cp_async16(sb + (uint32_t)(row * LDW + lq * 4) * 4u,
                       Arows + (size_t)row * NSd + k0 + lq * 4);
        }
        const uint32_t sbB = sb + (uint32_t)TILEF * 4u;
#pragma unroll
        for (int i = 0; i < 4; ++i) {
            const int row = i * 32 + lrow;
            cp_async16(sbB + (uint32_t)(row * LDW + lq * 4) * 4u,
                       Brows + (size_t)row * NSd + k0 + lq * 4);
        }
        asm volatile("cp.async.commit_group;" ::: "memory");
    };

    load_chunk(0);
    load_chunk(1);

    for (int c = 0; c < NCHUNK; ++c) {
        if (c + 1 < NCHUNK) asm volatile("cp.async.wait_group 1;" ::: "memory");
        else                asm volatile("cp.async.wait_group 0;" ::: "memory");
        __syncthreads();

        const float* cA = sm + (c & 1) * STAGEF;
        const float* cB = cA + TILEF;
#pragma unroll
        for (int s = 0; s < 4; ++s) {
            float a[4][4], b[4][2];
#pragma unroll
            for (int f = 0; f < 4; ++f) {
                const int r0 = (wr * 64 + f * 16 + grp) * LDW + s * 8 + tg;
                a[f][0] = cA[r0];
                a[f][1] = cA[r0 + 8 * LDW];
                a[f][2] = cA[r0 + 4];
                a[f][3] = cA[r0 + 8 * LDW + 4];
            }
#pragma unroll
            for (int g = 0; g < 4; ++g) {
                const int r0 = (wc * 32 + g * 8 + grp) * LDW + s * 8 + tg;
                b[g][0] = cB[r0];
                b[g][1] = cB[r0 + 4];
            }
#pragma unroll
            for (int f = 0; f < 4; ++f)
#pragma unroll
                for (int g = 0; g < 4; ++g)
                    mma_tf32(acc[f][g], a[f], b[g]);
        }
        __syncthreads();
        if (c + 2 < NCHUNK) load_chunk(c + 2);
    }
}

// ---------------- fp32 SGEMM (f32x2) — exact paths: xA and y ----------------
__device__ __forceinline__ ull pack2(float x) {
    ull r; unsigned u = __float_as_uint(x);
    asm("mov.b64 %0, {%1, %1};" : "=l"(r) : "r"(u));
    return r;
}
__device__ __forceinline__ void fma2(ull& d, ull a, ull b) {
    asm("fma.rn.f32x2 %0, %1, %2, %0;" : "+l"(d) : "l"(a), "l"(b));
}
__device__ __forceinline__ float2 unpack2(ull p) {
    unsigned lo, hi;
    asm("mov.b64 {%0, %1}, %2;" : "=r"(lo), "=r"(hi) : "l"(p));
    return make_float2(__uint_as_float(lo), __uint_as_float(hi));
}

__device__ __forceinline__ void gemm_tile_bt(
    const float* __restrict__ Ag, int lda,
    const float* __restrict__ Bg, int ldb,
    int m0, int n0, int K,
    ull acc[8][2], float* sA, float* sB) {
    const int tid = threadIdx.x;
    const int r0  = (tid >> 4) * 8;
    const int c0  = (tid & 15) * 4;
    const int lr  = tid >> 2;
    const int lk4 = (tid & 3) * 4;
    const int NSTEP = K >> 4;

    const float* apr0 = Ag + (size_t)(m0 + lr) * lda;
    const float* apr1 = Ag + (size_t)(m0 + lr + 64) * lda;

    auto store_sm = [&](int b2, float4 a0, float4 a1, float4 bb) {
        float* dA = sA + b2 * (BK * BM);
        dA[(lk4 + 0) * BM + lr] = a0.x;  dA[(lk4 + 1) * BM + lr] = a0.y;
        dA[(lk4 + 2) * BM + lr] = a0.z;  dA[(lk4 + 3) * BM + lr] = a0.w;
        dA[(lk4 + 0) * BM + lr + 64] = a1.x;  dA[(lk4 + 1) * BM + lr + 64] = a1.y;
        dA[(lk4 + 2) * BM + lr + 64] = a1.z;  dA[(lk4 + 3) * BM + lr + 64] = a1.w;
        float* dB = sB + b2 * (BK * BN);
        dB[(lk4 + 0) * BN + lr] = bb.x;  dB[(lk4 + 1) * BN + lr] = bb.y;
        dB[(lk4 + 2) * BN + lr] = bb.z;  dB[(lk4 + 3) * BN + lr] = bb.w;
    };

    float4 ra0 = *(const float4*)(apr0 + lk4);
    float4 ra1 = *(const float4*)(apr1 + lk4);
    float4 rb  = *(const float4*)(Bg + (size_t)(n0 + lr) * ldb + lk4);

    int buf = 0;
    store_sm(0, ra0, ra1, rb);
    __syncthreads();

    for (int s = 0; s < NSTEP; ++s) {
        float4 na0, na1, nb;
        if (s + 1 < NSTEP) {
            const int k0 = (s + 1) << 4;
            na0 = *(const float4*)(apr0 + k0 + lk4);
            na1 = *(const float4*)(apr1 + k0 + lk4);
            nb  = *(const float4*)(Bg + (size_t)(n0 + lr) * ldb + k0 + lk4);
        }
        const float* cA = sA + buf * (BK * BM) + r0;
        const float* cB = sB + buf * (BK * BN) + c0;
#pragma unroll
        for (int k = 0; k < BK; ++k) {
            float4 a0 = *(const float4*)(cA + k * BM);
            float4 a1 = *(const float4*)(cA + k * BM + 4);
            ull b0 = *(const ull*)(cB + k * BN);
            ull b1 = *(const ull*)(cB + k * BN + 2);
            ull p;
            p = pack2(a0.x); fma2(acc[0][0], p, b0); fma2(acc[0][1], p, b1);
            p = pack2(a0.y); fma2(acc[1][0], p, b0); fma2(acc[1][1], p, b1);
            p = pack2(a0.z); fma2(acc[2][0], p, b0); fma2(acc[2][1], p, b1);
            p = pack2(a0.w); fma2(acc[3][0], p, b0); fma2(acc[3][1], p, b1);
            p = pack2(a1.x); fma2(acc[4][0], p, b0); fma2(acc[4][1], p, b1);
            p = pack2(a1.y); fma2(acc[5][0], p, b0); fma2(acc[5][1], p, b1);
            p = pack2(a1.z); fma2(acc[6][0], p, b0); fma2(acc[6][1], p, b1);
            p = pack2(a1.w); fma2(acc[7][0], p, b0); fma2(acc[7][1], p, b1);
        }
        if (s + 1 < NSTEP) {
            store_sm(buf ^ 1, na0, na1, nb);
            __syncthreads();
            buf ^= 1;
        }
    }
    __syncthreads();
}

// ---------------- kernels ----------------
__global__ void k_init() { g_barrier = 0u; }

// tf32-rounded Bm and Bm^T
__global__ void k_prep(const float* __restrict__ Bm) {
    const int idx = blockIdx.x * 256 + threadIdx.x;
    const float r = tf32r(Bm[idx]);
    g_BmR[idx] = r;
    const int i = idx >> 9, j = idx & 511;
    g_BmT[j * NSd + i] = r;
}

// xA = x @ A^T + b   (exact fp32)
__global__ void __launch_bounds__(NTHREADS) k_xA(const float* __restrict__ x,
                                                 const float* __restrict__ A,
                                                 const float* __restrict__ b) {
    __shared__ float sA[2 * BK * BM];
    __shared__ float sB[2 * BK * BN];
    const int bid = blockIdx.x;
    const int m0 = (bid / TILES_NS) * BM;
    const int n0 = (bid % TILES_NS) * BN;
    ull acc[8][2];
#pragma unroll
    for (int i = 0; i < 8; ++i) { acc[i][0] = 0ull; acc[i][1] = 0ull; }
    gemm_tile_bt(x, NIN, A, NIN, m0, n0, NIN, acc, sA, sB);
    const int tid = threadIdx.x;
    const int r0 = (tid >> 4) * 8, c0 = (tid & 15) * 4;
    const float b0 = b[n0 + c0], b1 = b[n0 + c0 + 1], b2 = b[n0 + c0 + 2], b3 = b[n0 + c0 + 3];
#pragma unroll
    for (int r = 0; r < 8; ++r) {
        float2 lo = unpack2(acc[r][0]), hi = unpack2(acc[r][1]);
        float4 o = make_float4(lo.x + b0, lo.y + b1, hi.x + b2, hi.y + b3);
        *(float4*)&g_xA[(size_t)(m0 + r0 + r) * NSd + n0 + c0] = o;
    }
}

// Persistent tensor-core (mma.sync tf32) DEQ solver + g-phase + vjp
__global__ void __launch_bounds__(NTHREADS, 1) k_iter(const float* __restrict__ v) {
    extern __shared__ float sm[];
    __shared__ float red[NTHREADS];
    __shared__ int sdec;
    const uint32_t smb = smem_u32(sm);
    const int tid = threadIdx.x;
    const int w = tid >> 5, lane = tid & 31;
    const int wr = w >> 2, wc = w & 3;
    const int grp = lane >> 2, tg = lane & 3;
    const int m0 = blockIdx.x * 128;
    unsigned bar_exp = 0;
    int final_p = 0;
    float acc[4][4][4];

    for (int t = 1; t <= MAXITER; ++t) {
        const float* zin = g_zb[t & 1];
        float* zout = g_zb[(t - 1) & 1];
        float lnum = 0.f, lden = 0.f;

        if (t == 1) {
            // z1 = tanh(xA); res0 = 1 > eps always
            for (int i = tid; i < (128 * NSd) / 4; i += NTHREADS) {
                const size_t idx = (size_t)m0 * NSd + (size_t)i * 4;
                float4 xa = *(const float4*)&g_xA[idx];
                float4 z;
                z.x = tf32r(tanhf(xa.x)); z.y = tf32r(tanhf(xa.y));
                z.z = tf32r(tanhf(xa.z)); z.w = tf32r(tanhf(xa.w));
                const float s = z.x * z.x + z.y * z.y + z.z * z.z + z.w * z.w;
                lnum += s; lden += s;
                *(float4*)&zout[idx] = z;
            }
        } else {
            for (int nc = 0; nc < NPASS; ++nc) {
                mma_pass(zin + (size_t)m0 * NSd, g_BmR + (size_t)nc * 128 * NSd,
                         sm, smb, acc);
#pragma unroll
                for (int f = 0; f < 4; ++f) {
                    const int m = m0 + wr * 64 + f * 16 + grp;
#pragma unroll
                    for (int g = 0; g < 4; ++g) {
                        const int n = nc * 128 + wc * 32 + g * 8 + tg * 2;
#pragma unroll
                        for (int hr = 0; hr < 2; ++hr) {
                            const size_t idx = (size_t)(m + hr * 8) * NSd + n;
                            float2 xa = *(const float2*)&g_xA[idx];
                            float zx = tf32r(tanhf(xa.x + acc[f][g][hr * 2 + 0]));
                            float zy = tf32r(tanhf(xa.y + acc[f][g][hr * 2 + 1]));
                            float2 zp = *(const float2*)&zin[idx];
                            const float dx = zx - zp.x, dy = zy - zp.y;
                            lnum += dx * dx + dy * dy;
                            lden += zx * zx + zy * zy;
                            float2 o; o.x = zx; o.y = zy;
                            *(float2*)&zout[idx] = o;
                        }
                    }
                }
            }
        }

        float bnum = block_reduce(lnum, red);
        float bden = block_reduce(lden, red);
        if (tid == 0) {
            const int slot = t & 1;
            g_part[slot][2 * blockIdx.x]     = bnum;
            g_part[slot][2 * blockIdx.x + 1] = bden;
        }
        bar_exp += GRID_IT;
        grid_sync(bar_exp);

        if (tid == 0) {
            const int slot = t & 1;
            float num = 0.f, den = 0.f;
            for (int b2 = 0; b2 < GRID_IT; ++b2) {
                num += __ldcg(&g_part[slot][2 * b2]);
                den += __ldcg(&g_part[slot][2 * b2 + 1]);
            }
            const float res = sqrtf(num) / (sqrtf(den) + 1e-8f);
            sdec = (res <= EPS_STOP || t == MAXITER) ? 1 : 0;
        }
        __syncthreads();
        if (sdec) { final_p = (t - 1) & 1; break; }
    }

    if (blockIdx.x == 0 && tid == 0) g_zparity = final_p;

    // g-phase: g = v * (1 - tanh(xA + z* @ Bm^T)^2)
    const float* zs = g_zb[final_p];
    float* gbuf = g_zb[final_p ^ 1];
    for (int nc = 0; nc < NPASS; ++nc) {
        mma_pass(zs + (size_t)m0 * NSd, g_BmR + (size_t)nc * 128 * NSd, sm, smb, acc);
#pragma unroll
        for (int f = 0; f < 4; ++f) {
            const int m = m0 + wr * 64 + f * 16 + grp;
#pragma unroll
            for (int g = 0; g < 4; ++g) {
                const int n = nc * 128 + wc * 32 + g * 8 + tg * 2;
#pragma unroll
                for (int hr = 0; hr < 2; ++hr) {
                    const size_t idx = (size_t)(m + hr * 8) * NSd + n;
                    float2 xa = *(const float2*)&g_xA[idx];
                    float2 vv = *(const float2*)&v[idx];
                    float th, gx, gy;
                    th = tanhf(xa.x + acc[f][g][hr * 2 + 0]); gx = tf32r(vv.x * (1.f - th * th));
                    th = tanhf(xa.y + acc[f][g][hr * 2 + 1]); gy = tf32r(vv.y * (1.f - th * th));
                    float2 o; o.x = gx; o.y = gy;
                    *(float2*)&gbuf[idx] = o;
                }
            }
        }
    }
    __threadfence();
    __syncthreads();

    // vjp: vJ = g @ Bm = g @ (BmT)^T ; sum of squares
    float ls = 0.f;
    for (int nc = 0; nc < NPASS; ++nc) {
        mma_pass(gbuf + (size_t)m0 * NSd, g_BmT + (size_t)nc * 128 * NSd, sm, smb, acc);
#pragma unroll
        for (int f = 0; f < 4; ++f)
#pragma unroll
            for (int g = 0; g < 4; ++g)
#pragma unroll
                for (int r = 0; r < 4; ++r)
                    ls += acc[f][g][r] * acc[f][g][r];
    }
    float bs = block_reduce(ls, red);
    if (tid == 0) g_jacpart[blockIdx.x] = bs;
}

// y = z* @ Wh^T + bh
__global__ void __launch_bounds__(NTHREADS) k_y(const float* __restrict__ Wh,
                                                const float* __restrict__ bh,
                                                float* __restrict__ out) {
    __shared__ float sA[2 * BK * BM];
    __shared__ float sB[2 * BK * BN];
    const int parity = g_zparity;
    const float* zs = g_zb[parity];
    const int m0 = blockIdx.x * BM;
    ull acc[8][2];
#pragma unroll
    for (int i = 0; i < 8; ++i) { acc[i][0] = 0ull; acc[i][1] = 0ull; }
    gemm_tile_bt(zs, NSd, Wh, NSd, m0, 0, NSd, acc, sA, sB);
    const int tid = threadIdx.x;
    const int r0 = (tid >> 4) * 8, c0 = (tid & 15) * 4;
    const float b0 = bh[c0], b1 = bh[c0 + 1], b2 = bh[c0 + 2], b3 = bh[c0 + 3];
#pragma unroll
    for (int r = 0; r < 8; ++r) {
        float2 lo = unpack2(acc[r][0]), hi = unpack2(acc[r][1]);
        float4 o = make_float4(lo.x + b0, lo.y + b1, hi.x + b2, hi.y + b3);
        *(float4*)&out[(size_t)(m0 + r0 + r) * NOUT + c0] = o;
    }
}

__global__ void k_jac(float* __restrict__ out) {
    __shared__ float sred[NTHREADS];
    const int tid = threadIdx.x;
    float s = (tid < GRID_IT) ? g_jacpart[tid] : 0.f;
    sred[tid] = s; __syncthreads();
    for (int o = 128; o > 0; o >>= 1) {
        if (tid < o) sred[tid] += sred[tid + o];
        __syncthreads();
    }
    if (tid == 0) out[(size_t)NM * NOUT] = sred[0] / ((float)NM * (float)NSd);
}

// ---------------- launcher ----------------
extern "C" void kernel_launch(void* const* d_in, const int* in_sizes, int n_in,
                              void* d_out, int out_size) {
    const float* x   = (const float*)d_in[0];
    const float* A   = (const float*)d_in[1];
    const float* Bm  = (const float*)d_in[2];
    const float* b   = (const float*)d_in[3];
    const float* Wh  = (const float*)d_in[4];
    const float* bh  = (const float*)d_in[5];
    const float* v   = (const float*)d_in[6];
    float* out = (float*)d_out;

    static int configured = 0;
    if (!configured) {
        cudaFuncSetAttribute(k_iter, cudaFuncAttributeMaxDynamicSharedMemorySize, SMEM_DYN);
        configured = 1;
    }

    k_init<<<1, 1>>>();
    k_prep<<<(NSd * NSd) / 256, 256>>>(Bm);
    k_xA<<<NTILES, NTHREADS>>>(x, A, b);
    k_iter<<<GRID_IT, NTHREADS, SMEM_DYN>>>(v);
    k_y<<<TILES_M, NTHREADS>>>(Wh, bh, out);
    k_jac<<<1, NTHREADS>>>(out);
}

// round 6
// speedup vs baseline: 2.2968x; 1.1100x over previous
#include <cuda_runtime.h>
#include <math.h>
#include <stdint.h>

typedef unsigned long long ull;

#define NM    16384
#define NSd   512
#define NIN   64
#define NOUT  64
#define BM    128
#define BN    64
#define BK    16
#define NTHREADS 256
#define TILES_M   (NM / BM)            // 128
#define TILES_NS  (NSd / BN)           // 8
#define NTILES    (TILES_M * TILES_NS) // 1024
#define MAXITER   200
#define EPS_STOP  1e-3f

// ---- tensor (mma.sync tf32) path constants ----
#define GRID_IT   128                  // persistent CTAs, one M=128 tile each
#define NTH_IT    512                  // 16 warps
#define KC        32                   // K per SMEM chunk
#define NCHUNK    16                   // 512 / 32
#define NPASS     2                    // N covered in 2 passes of 256
#define BROWS     256                  // B rows staged per pass
#define LDW       36                   // padded smem row (floats) -> conflict-free frag LDS
#define TILEF_A   (128 * LDW)          // 4608 floats
#define TILEF_B   (BROWS * LDW)        // 9216 floats
#define STAGEF    (TILEF_A + TILEF_B)  // 13824 floats = 55296 B
#define NSTAGE    3
#define SMEM_DYN  (NSTAGE * STAGEF * 4)  // 165888 B

// ---------------- device scratch ----------------
__device__ float g_xA[NM * NSd];          // x@A^T + b (exact fp32)
__device__ float g_zb[2][NM * NSd];       // ping-pong z buffers (one reused for g)
__device__ float g_BmR[NSd * NSd];        // tf32-rounded Bm
__device__ float g_BmT[NSd * NSd];        // tf32-rounded Bm^T
__device__ unsigned g_barrier;
__device__ int g_zparity;
__device__ float g_part[2][2 * GRID_IT];
__device__ float g_jacpart[GRID_IT];

// ---------------- small helpers ----------------
__device__ __forceinline__ uint32_t smem_u32(const void* p) {
    uint32_t a;
    asm("{ .reg .u64 t; cvta.to.shared.u64 t, %1; cvt.u32.u64 %0, t; }" : "=r"(a) : "l"(p));
    return a;
}
__device__ __forceinline__ float tf32r(float x) {
    uint32_t o;
    asm("cvt.rna.tf32.f32 %0, %1;" : "=r"(o) : "f"(x));
    return __uint_as_float(o);
}
__device__ __forceinline__ void cp_async16(uint32_t saddr, const float* g) {
    asm volatile("cp.async.cg.shared.global [%0], [%1], 16;" :: "r"(saddr), "l"(g) : "memory");
}
__device__ __forceinline__ void mma_tf32(float c[4], const float a[4], const float b[2]) {
    asm volatile(
        "mma.sync.aligned.m16n8k8.row.col.f32.tf32.tf32.f32 "
        "{%0,%1,%2,%3}, {%4,%5,%6,%7}, {%8,%9}, {%0,%1,%2,%3};"
        : "+f"(c[0]), "+f"(c[1]), "+f"(c[2]), "+f"(c[3])
        : "r"(__float_as_uint(a[0])), "r"(__float_as_uint(a[1])),
          "r"(__float_as_uint(a[2])), "r"(__float_as_uint(a[3])),
          "r"(__float_as_uint(b[0])), "r"(__float_as_uint(b[1])));
}

// ---------------- grid barrier (all CTAs resident: 128 <= #SMs) ----------------
__device__ __forceinline__ void grid_sync(unsigned expected) {
    __syncthreads();
    if (threadIdx.x == 0) {
        __threadfence();
        unsigned arr = atomicAdd(&g_barrier, 1u) + 1u;
        if (arr < expected) {
            while (*(volatile unsigned*)&g_barrier < expected) { }
        }
        __threadfence();
    }
    __syncthreads();
}

// 512-thread tree reduce (deterministic, identical across CTAs)
__device__ __forceinline__ float block_reduce512(float v, float* sred) {
    const int tid = threadIdx.x;
    sred[tid] = v; __syncthreads();
#pragma unroll
    for (int o = NTH_IT / 2; o > 0; o >>= 1) {
        if (tid < o) sred[tid] += sred[tid + o];
        __syncthreads();
    }
    float r = sred[0];
    __syncthreads();
    return r;
}

// ---------------- mma.sync tf32 pass: acc[128x256] = Arows(128x512) @ Brows(256x512)^T ----
// Warp grid 2(M) x 8(N); warp tile 64x32; frags m16n8k8; 3-stage cp.async pipeline,
// one __syncthreads per chunk.
__device__ void mma_pass(const float* __restrict__ Arows,
                         const float* __restrict__ Brows,
                         float* __restrict__ sm, uint32_t smb,
                         float acc[4][4][4]) {
    const int tid = threadIdx.x;
    const int w = tid >> 5, lane = tid & 31;
    const int wr = w >> 3, wc = w & 7;
    const int grp = lane >> 2, tg = lane & 3;

#pragma unroll
    for (int f = 0; f < 4; ++f)
#pragma unroll
        for (int g = 0; g < 4; ++g)
#pragma unroll
            for (int r = 0; r < 4; ++r) acc[f][g][r] = 0.f;

    __syncthreads();   // previous users of smem done

    const int arow = tid >> 2, aq0 = (tid & 3) * 2;   // A: 128 rows, 2 x 16B / thread
    const int brow = tid >> 1, bq0 = (tid & 1) * 4;   // B: 256 rows, 4 x 16B / thread
    const float* aptr = Arows + (size_t)arow * NSd;
    const float* bptr = Brows + (size_t)brow * NSd;

    auto load_chunk = [&](int c, int stage) {
        const uint32_t sb = smb + (uint32_t)(stage * STAGEF) * 4u;
        const int k0 = c * KC;
#pragma unroll
        for (int i = 0; i < 2; ++i) {
            const int q = aq0 + i;
            cp_async16(sb + (uint32_t)(arow * LDW + q * 4) * 4u, aptr + k0 + q * 4);
        }
        const uint32_t sbB = sb + (uint32_t)TILEF_A * 4u;
#pragma unroll
        for (int i = 0; i < 4; ++i) {
            const int q = bq0 + i;
            cp_async16(sbB + (uint32_t)(brow * LDW + q * 4) * 4u, bptr + k0 + q * 4);
        }
        asm volatile("cp.async.commit_group;" ::: "memory");
    };

    load_chunk(0, 0);
    load_chunk(1, 1);

    int cstage = 0, lstage = 2;
    for (int c = 0; c < NCHUNK; ++c) {
        if (c + 1 < NCHUNK) asm volatile("cp.async.wait_group 1;" ::: "memory");
        else                asm volatile("cp.async.wait_group 0;" ::: "memory");
        __syncthreads();   // chunk c visible everywhere; stage being refilled is free

        if (c + 2 < NCHUNK) {
            load_chunk(c + 2, lstage);
            lstage = (lstage + 1 == NSTAGE) ? 0 : lstage + 1;
        }

        const float* cA = sm + cstage * STAGEF;
        const float* cB = cA + TILEF_A;
#pragma unroll
        for (int s = 0; s < 4; ++s) {
            float a[4][4], b[4][2];
#pragma unroll
            for (int f = 0; f < 4; ++f) {
                const int r0 = (wr * 64 + f * 16 + grp) * LDW + s * 8 + tg;
                a[f][0] = cA[r0];
                a[f][1] = cA[r0 + 8 * LDW];
                a[f][2] = cA[r0 + 4];
                a[f][3] = cA[r0 + 8 * LDW + 4];
            }
#pragma unroll
            for (int g = 0; g < 4; ++g) {
                const int r0 = (wc * 32 + g * 8 + grp) * LDW + s * 8 + tg;
                b[g][0] = cB[r0];
                b[g][1] = cB[r0 + 4];
            }
#pragma unroll
            for (int f = 0; f < 4; ++f)
#pragma unroll
                for (int g = 0; g < 4; ++g)
                    mma_tf32(acc[f][g], a[f], b[g]);
        }
        cstage = (cstage + 1 == NSTAGE) ? 0 : cstage + 1;
    }
}

// ---------------- fp32 SGEMM (f32x2) — exact paths: xA and y ----------------
__device__ __forceinline__ ull pack2(float x) {
    ull r; unsigned u = __float_as_uint(x);
    asm("mov.b64 %0, {%1, %1};" : "=l"(r) : "r"(u));
    return r;
}
__device__ __forceinline__ void fma2(ull& d, ull a, ull b) {
    asm("fma.rn.f32x2 %0, %1, %2, %0;" : "+l"(d) : "l"(a), "l"(b));
}
__device__ __forceinline__ float2 unpack2(ull p) {
    unsigned lo, hi;
    asm("mov.b64 {%0, %1}, %2;" : "=r"(lo), "=r"(hi) : "l"(p));
    return make_float2(__uint_as_float(lo), __uint_as_float(hi));
}

__device__ __forceinline__ void gemm_tile_bt(
    const float* __restrict__ Ag, int lda,
    const float* __restrict__ Bg, int ldb,
    int m0, int n0, int K,
    ull acc[8][2], float* sA, float* sB) {
    const int tid = threadIdx.x;
    const int r0  = (tid >> 4) * 8;
    const int c0  = (tid & 15) * 4;
    const int lr  = tid >> 2;
    const int lk4 = (tid & 3) * 4;
    const int NSTEP = K >> 4;

    const float* apr0 = Ag + (size_t)(m0 + lr) * lda;
    const float* apr1 = Ag + (size_t)(m0 + lr + 64) * lda;

    auto store_sm = [&](int b2, float4 a0, float4 a1, float4 bb) {
        float* dA = sA + b2 * (BK * BM);
        dA[(lk4 + 0) * BM + lr] = a0.x;  dA[(lk4 + 1) * BM + lr] = a0.y;
        dA[(lk4 + 2) * BM + lr] = a0.z;  dA[(lk4 + 3) * BM + lr] = a0.w;
        dA[(lk4 + 0) * BM + lr + 64] = a1.x;  dA[(lk4 + 1) * BM + lr + 64] = a1.y;
        dA[(lk4 + 2) * BM + lr + 64] = a1.z;  dA[(lk4 + 3) * BM + lr + 64] = a1.w;
        float* dB = sB + b2 * (BK * BN);
        dB[(lk4 + 0) * BN + lr] = bb.x;  dB[(lk4 + 1) * BN + lr] = bb.y;
        dB[(lk4 + 2) * BN + lr] = bb.z;  dB[(lk4 + 3) * BN + lr] = bb.w;
    };

    float4 ra0 = *(const float4*)(apr0 + lk4);
    float4 ra1 = *(const float4*)(apr1 + lk4);
    float4 rb  = *(const float4*)(Bg + (size_t)(n0 + lr) * ldb + lk4);

    int buf = 0;
    store_sm(0, ra0, ra1, rb);
    __syncthreads();

    for (int s = 0; s < NSTEP; ++s) {
        float4 na0, na1, nb;
        if (s + 1 < NSTEP) {
            const int k0 = (s + 1) << 4;
            na0 = *(const float4*)(apr0 + k0 + lk4);
            na1 = *(const float4*)(apr1 + k0 + lk4);
            nb  = *(const float4*)(Bg + (size_t)(n0 + lr) * ldb + k0 + lk4);
        }
        const float* cA = sA + buf * (BK * BM) + r0;
        const float* cB = sB + buf * (BK * BN) + c0;
#pragma unroll
        for (int k = 0; k < BK; ++k) {
            float4 a0 = *(const float4*)(cA + k * BM);
            float4 a1 = *(const float4*)(cA + k * BM + 4);
            ull b0 = *(const ull*)(cB + k * BN);
            ull b1 = *(const ull*)(cB + k * BN + 2);
            ull p;
            p = pack2(a0.x); fma2(acc[0][0], p, b0); fma2(acc[0][1], p, b1);
            p = pack2(a0.y); fma2(acc[1][0], p, b0); fma2(acc[1][1], p, b1);
            p = pack2(a0.z); fma2(acc[2][0], p, b0); fma2(acc[2][1], p, b1);
            p = pack2(a0.w); fma2(acc[3][0], p, b0); fma2(acc[3][1], p, b1);
            p = pack2(a1.x); fma2(acc[4][0], p, b0); fma2(acc[4][1], p, b1);
            p = pack2(a1.y); fma2(acc[5][0], p, b0); fma2(acc[5][1], p, b1);
            p = pack2(a1.z); fma2(acc[6][0], p, b0); fma2(acc[6][1], p, b1);
            p = pack2(a1.w); fma2(acc[7][0], p, b0); fma2(acc[7][1], p, b1);
        }
        if (s + 1 < NSTEP) {
            store_sm(buf ^ 1, na0, na1, nb);
            __syncthreads();
            buf ^= 1;
        }
    }
    __syncthreads();
}

// ---------------- kernels ----------------
__global__ void k_init() { g_barrier = 0u; }

// tf32-rounded Bm and Bm^T
__global__ void k_prep(const float* __restrict__ Bm) {
    const int idx = blockIdx.x * 256 + threadIdx.x;
    const float r = tf32r(Bm[idx]);
    g_BmR[idx] = r;
    const int i = idx >> 9, j = idx & 511;
    g_BmT[j * NSd + i] = r;
}

// xA = x @ A^T + b   (exact fp32)
__global__ void __launch_bounds__(NTHREADS) k_xA(const float* __restrict__ x,
                                                 const float* __restrict__ A,
                                                 const float* __restrict__ b) {
    __shared__ float sA[2 * BK * BM];
    __shared__ float sB[2 * BK * BN];
    const int bid = blockIdx.x;
    const int m0 = (bid / TILES_NS) * BM;
    const int n0 = (bid % TILES_NS) * BN;
    ull acc[8][2];
#pragma unroll
    for (int i = 0; i < 8; ++i) { acc[i][0] = 0ull; acc[i][1] = 0ull; }
    gemm_tile_bt(x, NIN, A, NIN, m0, n0, NIN, acc, sA, sB);
    const int tid = threadIdx.x;
    const int r0 = (tid >> 4) * 8, c0 = (tid & 15) * 4;
    const float b0 = b[n0 + c0], b1 = b[n0 + c0 + 1], b2 = b[n0 + c0 + 2], b3 = b[n0 + c0 + 3];
#pragma unroll
    for (int r = 0; r < 8; ++r) {
        float2 lo = unpack2(acc[r][0]), hi = unpack2(acc[r][1]);
        float4 o = make_float4(lo.x + b0, lo.y + b1, hi.x + b2, hi.y + b3);
        *(float4*)&g_xA[(size_t)(m0 + r0 + r) * NSd + n0 + c0] = o;
    }
}

// Persistent tensor-core (mma.sync tf32) DEQ solver + g-phase + vjp; 512 threads.
__global__ void __launch_bounds__(NTH_IT, 1) k_iter(const float* __restrict__ v) {
    extern __shared__ float sm[];
    __shared__ float red[NTH_IT];
    const uint32_t smb = smem_u32(sm);
    const int tid = threadIdx.x;
    const int w = tid >> 5, lane = tid & 31;
    const int wr = w >> 3, wc = w & 7;
    const int grp = lane >> 2, tg = lane & 3;
    const int m0 = blockIdx.x * 128;
    unsigned bar_exp = 0;
    int final_p = 0;
    float acc[4][4][4];

    for (int t = 1; t <= MAXITER; ++t) {
        const float* zin = g_zb[t & 1];
        float* zout = g_zb[(t - 1) & 1];
        float lnum = 0.f, lden = 0.f;

        if (t == 1) {
            // z1 = tanh(xA); res0 = 1 > eps always
            for (int i = tid; i < (128 * NSd) / 4; i += NTH_IT) {
                const size_t idx = (size_t)m0 * NSd + (size_t)i * 4;
                float4 xa = *(const float4*)&g_xA[idx];
                float4 z;
                z.x = tf32r(tanhf(xa.x)); z.y = tf32r(tanhf(xa.y));
                z.z = tf32r(tanhf(xa.z)); z.w = tf32r(tanhf(xa.w));
                const float s = z.x * z.x + z.y * z.y + z.z * z.z + z.w * z.w;
                lnum += s; lden += s;
                *(float4*)&zout[idx] = z;
            }
        } else {
            for (int nc = 0; nc < NPASS; ++nc) {
                mma_pass(zin + (size_t)m0 * NSd, g_BmR + (size_t)nc * BROWS * NSd,
                         sm, smb, acc);
#pragma unroll
                for (int f = 0; f < 4; ++f) {
                    const int m = m0 + wr * 64 + f * 16 + grp;
#pragma unroll
                    for (int g = 0; g < 4; ++g) {
                        const int n = nc * BROWS + wc * 32 + g * 8 + tg * 2;
#pragma unroll
                        for (int hr = 0; hr < 2; ++hr) {
                            const size_t idx = (size_t)(m + hr * 8) * NSd + n;
                            float2 xa = *(const float2*)&g_xA[idx];
                            float zx = tf32r(tanhf(xa.x + acc[f][g][hr * 2 + 0]));
                            float zy = tf32r(tanhf(xa.y + acc[f][g][hr * 2 + 1]));
                            float2 zp = *(const float2*)&zin[idx];
                            const float dx = zx - zp.x, dy = zy - zp.y;
                            lnum += dx * dx + dy * dy;
                            lden += zx * zx + zy * zy;
                            float2 o; o.x = zx; o.y = zy;
                            *(float2*)&zout[idx] = o;
                        }
                    }
                }
            }
        }

        float bnum = block_reduce512(lnum, red);
        float bden = block_reduce512(lden, red);
        if (tid == 0) {
            const int slot = t & 1;
            g_part[slot][2 * blockIdx.x]     = bnum;
            g_part[slot][2 * blockIdx.x + 1] = bden;
        }
        bar_exp += GRID_IT;
        grid_sync(bar_exp);

        // parallel decision: identical deterministic computation in every thread/CTA
        {
            const int slot = t & 1;
            float pn = 0.f, pd = 0.f;
            if (tid < GRID_IT) {
                pn = __ldcg(&g_part[slot][2 * tid]);
                pd = __ldcg(&g_part[slot][2 * tid + 1]);
            }
            float num = block_reduce512(pn, red);
            float den = block_reduce512(pd, red);
            const float res = sqrtf(num) / (sqrtf(den) + 1e-8f);
            if (res <= EPS_STOP || t == MAXITER) { final_p = (t - 1) & 1; break; }
        }
    }

    if (blockIdx.x == 0 && tid == 0) g_zparity = final_p;

    // g-phase: g = v * (1 - tanh(xA + z* @ Bm^T)^2)
    const float* zs = g_zb[final_p];
    float* gbuf = g_zb[final_p ^ 1];
    for (int nc = 0; nc < NPASS; ++nc) {
        mma_pass(zs + (size_t)m0 * NSd, g_BmR + (size_t)nc * BROWS * NSd, sm, smb, acc);
#pragma unroll
        for (int f = 0; f < 4; ++f) {
            const int m = m0 + wr * 64 + f * 16 + grp;
#pragma unroll
            for (int g = 0; g < 4; ++g) {
                const int n = nc * BROWS + wc * 32 + g * 8 + tg * 2;
#pragma unroll
                for (int hr = 0; hr < 2; ++hr) {
                    const size_t idx = (size_t)(m + hr * 8) * NSd + n;
                    float2 xa = *(const float2*)&g_xA[idx];
                    float2 vv = *(const float2*)&v[idx];
                    float th, gx, gy;
                    th = tanhf(xa.x + acc[f][g][hr * 2 + 0]); gx = tf32r(vv.x * (1.f - th * th));
                    th = tanhf(xa.y + acc[f][g][hr * 2 + 1]); gy = tf32r(vv.y * (1.f - th * th));
                    float2 o; o.x = gx; o.y = gy;
                    *(float2*)&gbuf[idx] = o;
                }
            }
        }
    }
    __threadfence();
    __syncthreads();

    // vjp: vJ = g @ Bm = g @ (BmT)^T ; sum of squares
    float ls = 0.f;
    for (int nc = 0; nc < NPASS; ++nc) {
        mma_pass(gbuf + (size_t)m0 * NSd, g_BmT + (size_t)nc * BROWS * NSd, sm, smb, acc);
#pragma unroll
        for (int f = 0; f < 4; ++f)
#pragma unroll
            for (int g = 0; g < 4; ++g)
#pragma unroll
                for (int r = 0; r < 4; ++r)
                    ls += acc[f][g][r] * acc[f][g][r];
    }
    float bs = block_reduce512(ls, red);
    if (tid == 0) g_jacpart[blockIdx.x] = bs;
}

// y = z* @ Wh^T + bh
__global__ void __launch_bounds__(NTHREADS) k_y(const float* __restrict__ Wh,
                                                const float* __restrict__ bh,
                                                float* __restrict__ out) {
    __shared__ float sA[2 * BK * BM];
    __shared__ float sB[2 * BK * BN];
    const int parity = g_zparity;
    const float* zs = g_zb[parity];
    const int m0 = blockIdx.x * BM;
    ull acc[8][2];
#pragma unroll
    for (int i = 0; i < 8; ++i) { acc[i][0] = 0ull; acc[i][1] = 0ull; }
    gemm_tile_bt(zs, NSd, Wh, NSd, m0, 0, NSd, acc, sA, sB);
    const int tid = threadIdx.x;
    const int r0 = (tid >> 4) * 8, c0 = (tid & 15) * 4;
    const float b0 = bh[c0], b1 = bh[c0 + 1], b2 = bh[c0 + 2], b3 = bh[c0 + 3];
#pragma unroll
    for (int r = 0; r < 8; ++r) {
        float2 lo = unpack2(acc[r][0]), hi = unpack2(acc[r][1]);
        float4 o = make_float4(lo.x + b0, lo.y + b1, hi.x + b2, hi.y + b3);
        *(float4*)&out[(size_t)(m0 + r0 + r) * NOUT + c0] = o;
    }
}

__global__ void k_jac(float* __restrict__ out) {
    __shared__ float sred[NTHREADS];
    const int tid = threadIdx.x;
    float s = (tid < GRID_IT) ? g_jacpart[tid] : 0.f;
    sred[tid] = s; __syncthreads();
    for (int o = 128; o > 0; o >>= 1) {
        if (tid < o) sred[tid] += sred[tid + o];
        __syncthreads();
    }
    if (tid == 0) out[(size_t)NM * NOUT] = sred[0] / ((float)NM * (float)NSd);
}

// ---------------- launcher ----------------
extern "C" void kernel_launch(void* const* d_in, const int* in_sizes, int n_in,
                              void* d_out, int out_size) {
    const float* x   = (const float*)d_in[0];
    const float* A   = (const float*)d_in[1];
    const float* Bm  = (const float*)d_in[2];
    const float* b   = (const float*)d_in[3];
    const float* Wh  = (const float*)d_in[4];
    const float* bh  = (const float*)d_in[5];
    const float* v   = (const float*)d_in[6];
    float* out = (float*)d_out;

    static int configured = 0;
    if (!configured) {
        cudaFuncSetAttribute(k_iter, cudaFuncAttributeMaxDynamicSharedMemorySize, SMEM_DYN);
        configured = 1;
    }

    k_init<<<1, 1>>>();
    k_prep<<<(NSd * NSd) / 256, 256>>>(Bm);
    k_xA<<<NTILES, NTHREADS>>>(x, A, b);
    k_iter<<<GRID_IT, NTH_IT, SMEM_DYN>>>(v);
    k_y<<<TILES_M, NTHREADS>>>(Wh, bh, out);
    k_jac<<<1, NTHREADS>>>(out);
}

// round 7
// speedup vs baseline: 3.9183x; 1.7060x over previous
#include <cuda_runtime.h>
#include <cuda_fp16.h>
#include <math.h>
#include <stdint.h>

typedef unsigned long long ull;

#define NM    16384
#define NSd   512
#define NIN   64
#define NOUT  64
#define BM    128
#define BN    64
#define BK    16
#define NTHREADS 256
#define TILES_M   (NM / BM)            // 128
#define TILES_NS  (NSd / BN)           // 8
#define NTILES    (TILES_M * TILES_NS) // 1024
#define MAXITER   200
#define EPS_STOP  1e-3f

// ---- fp16 mma.sync path constants ----
#define GRID_IT   128                  // persistent CTAs, one M=128 tile each
#define NTH_IT    512                  // 16 warps
#define KC        64                   // K (halves) per SMEM chunk
#define NCHUNK    8                    // 512 / 64
#define NPASS     2                    // N covered in 2 passes of 256
#define BROWS     256                  // B rows staged per pass
#define LDH       72                   // padded smem row in halves (144 B) -> conflict-free ldmatrix
#define LDB       (LDH * 2)            // row stride bytes = 144
#define TILEH_A   (128 * LDH)          // 9216 halves
#define TILEH_B   (BROWS * LDH)        // 18432 halves
#define STAGEH    (TILEH_A + TILEH_B)  // 27648 halves = 55296 B
#define NSTAGE    3
#define SMEM_DYN  (NSTAGE * STAGEH * 2)  // 165888 B

// ---------------- device scratch ----------------
__device__ float  g_xA[NM * NSd];          // x@A^T + b (exact fp32)
__device__ __half g_zh[2][NM * NSd];       // fp16 ping-pong z buffers (one reused for g)
__device__ float  g_zf[NM * NSd];          // fp32 copy of z* for k_y
__device__ __half g_BmH[NSd * NSd];        // fp16 Bm  (rows = n, cols = k)
__device__ __half g_BmTH[NSd * NSd];       // fp16 Bm^T (rows = n for vjp)
__device__ unsigned g_barrier;
__device__ int g_zparity;
__device__ float g_part[2][2 * GRID_IT];
__device__ float g_jacpart[GRID_IT];

// ---------------- small helpers ----------------
__device__ __forceinline__ uint32_t smem_u32(const void* p) {
    uint32_t a;
    asm("{ .reg .u64 t; cvta.to.shared.u64 t, %1; cvt.u32.u64 %0, t; }" : "=r"(a) : "l"(p));
    return a;
}
__device__ __forceinline__ void cp_async16(uint32_t saddr, const void* g) {
    asm volatile("cp.async.cg.shared.global [%0], [%1], 16;" :: "r"(saddr), "l"(g) : "memory");
}
__device__ __forceinline__ void ldmatrix_x4(uint32_t r[4], uint32_t addr) {
    asm volatile("ldmatrix.sync.aligned.m8n8.x4.shared.b16 {%0,%1,%2,%3}, [%4];"
        : "=r"(r[0]), "=r"(r[1]), "=r"(r[2]), "=r"(r[3]) : "r"(addr));
}
__device__ __forceinline__ void mma_f16(float c[4], const uint32_t a[4], const uint32_t b[2]) {
    asm volatile(
        "mma.sync.aligned.m16n8k16.row.col.f32.f16.f16.f32 "
        "{%0,%1,%2,%3}, {%4,%5,%6,%7}, {%8,%9}, {%0,%1,%2,%3};"
        : "+f"(c[0]), "+f"(c[1]), "+f"(c[2]), "+f"(c[3])
        : "r"(a[0]), "r"(a[1]), "r"(a[2]), "r"(a[3]), "r"(b[0]), "r"(b[1]));
}

// ---------------- grid barrier (all CTAs resident: 128 <= #SMs) ----------------
__device__ __forceinline__ void grid_sync(unsigned expected) {
    __syncthreads();
    if (threadIdx.x == 0) {
        __threadfence();
        unsigned arr = atomicAdd(&g_barrier, 1u) + 1u;
        if (arr < expected) {
            while (*(volatile unsigned*)&g_barrier < expected) { }
        }
        __threadfence();
    }
    __syncthreads();
}

// 512-thread tree reduce (deterministic, identical across CTAs)
__device__ __forceinline__ float block_reduce512(float v, float* sred) {
    const int tid = threadIdx.x;
    sred[tid] = v; __syncthreads();
#pragma unroll
    for (int o = NTH_IT / 2; o > 0; o >>= 1) {
        if (tid < o) sred[tid] += sred[tid + o];
        __syncthreads();
    }
    float r = sred[0];
    __syncthreads();
    return r;
}

// ---------------- fp16 mma pass: acc[128x256] = Arows(128x512) @ Brows(256x512)^T ----
// Warp grid 2(M) x 8(N); warp tile 64x32; frags m16n8k16 via ldmatrix; 3-stage
// cp.async pipeline, one __syncthreads per 64-k chunk.
__device__ void mma_pass_f16(const __half* __restrict__ Arows,
                             const __half* __restrict__ Brows,
                             uint32_t smb, float acc[4][4][4]) {
    const int tid = threadIdx.x;
    const int w = tid >> 5, lane = tid & 31;
    const int wr = w >> 3, wc = w & 7;

#pragma unroll
    for (int f = 0; f < 4; ++f)
#pragma unroll
        for (int g = 0; g < 4; ++g)
#pragma unroll
            for (int r = 0; r < 4; ++r) acc[f][g][r] = 0.f;

    __syncthreads();   // previous users of smem done

    const int lrow = tid >> 3, lseg = tid & 7;   // 64 rows per i-step, 8 x 16B per row

    auto load_chunk = [&](int c, int stage) {
        const uint32_t sb = smb + (uint32_t)(stage * STAGEH * 2);
        const int k0 = c * KC;
#pragma unroll
        for (int i = 0; i < 2; ++i) {            // A: 128 rows x 8 segs
            const int row = i * 64 + lrow;
            cp_async16(sb + (uint32_t)(row * LDB + lseg * 16),
                       Arows + (size_t)row * NSd + k0 + lseg * 8);
        }
        const uint32_t sbB = sb + (uint32_t)(TILEH_A * 2);
#pragma unroll
        for (int i = 0; i < 4; ++i) {            // B: 256 rows x 8 segs
            const int row = i * 64 + lrow;
            cp_async16(sbB + (uint32_t)(row * LDB + lseg * 16),
                       Brows + (size_t)row * NSd + k0 + lseg * 8);
        }
        asm volatile("cp.async.commit_group;" ::: "memory");
    };

    load_chunk(0, 0);
    load_chunk(1, 1);

    const int rsel = lane & 15;
    const int ksel = (lane >> 4) << 3;   // 0 or 8 halves

    int cstage = 0, lstage = 2;
    for (int c = 0; c < NCHUNK; ++c) {
        if (c + 1 < NCHUNK) asm volatile("cp.async.wait_group 1;" ::: "memory");
        else                asm volatile("cp.async.wait_group 0;" ::: "memory");
        __syncthreads();

        if (c + 2 < NCHUNK) {
            load_chunk(c + 2, lstage);
            lstage = (lstage + 1 == NSTAGE) ? 0 : lstage + 1;
        }

        const uint32_t sA = smb + (uint32_t)(cstage * STAGEH * 2);
        const uint32_t sB = sA + (uint32_t)(TILEH_A * 2);
#pragma unroll
        for (int ks = 0; ks < 4; ++ks) {
            const uint32_t koff = (uint32_t)((ks * 16 + ksel) * 2);
            uint32_t a[4][4], bf[2][4];
#pragma unroll
            for (int f = 0; f < 4; ++f)
                ldmatrix_x4(a[f], sA + (uint32_t)((wr * 64 + f * 16 + rsel) * LDB) + koff);
#pragma unroll
            for (int h = 0; h < 2; ++h)
                ldmatrix_x4(bf[h], sB + (uint32_t)((wc * 32 + h * 16 + rsel) * LDB) + koff);
#pragma unroll
            for (int f = 0; f < 4; ++f) {
                { uint32_t b2[2] = {bf[0][0], bf[0][2]}; mma_f16(acc[f][0], a[f], b2); }
                { uint32_t b2[2] = {bf[0][1], bf[0][3]}; mma_f16(acc[f][1], a[f], b2); }
                { uint32_t b2[2] = {bf[1][0], bf[1][2]}; mma_f16(acc[f][2], a[f], b2); }
                { uint32_t b2[2] = {bf[1][1], bf[1][3]}; mma_f16(acc[f][3], a[f], b2); }
            }
        }
        cstage = (cstage + 1 == NSTAGE) ? 0 : cstage + 1;
    }
}

// ---------------- fp32 SGEMM (f32x2) — exact paths: xA and y ----------------
__device__ __forceinline__ ull pack2(float x) {
    ull r; unsigned u = __float_as_uint(x);
    asm("mov.b64 %0, {%1, %1};" : "=l"(r) : "r"(u));
    return r;
}
__device__ __forceinline__ void fma2(ull& d, ull a, ull b) {
    asm("fma.rn.f32x2 %0, %1, %2, %0;" : "+l"(d) : "l"(a), "l"(b));
}
__device__ __forceinline__ float2 unpack2(ull p) {
    unsigned lo, hi;
    asm("mov.b64 {%0, %1}, %2;" : "=r"(lo), "=r"(hi) : "l"(p));
    return make_float2(__uint_as_float(lo), __uint_as_float(hi));
}

__device__ __forceinline__ void gemm_tile_bt(
    const float* __restrict__ Ag, int lda,
    const float* __restrict__ Bg, int ldb,
    int m0, int n0, int K,
    ull acc[8][2], float* sA, float* sB) {
    const int tid = threadIdx.x;
    const int r0  = (tid >> 4) * 8;
    const int c0  = (tid & 15) * 4;
    const int lr  = tid >> 2;
    const int lk4 = (tid & 3) * 4;
    const int NSTEP = K >> 4;

    const float* apr0 = Ag + (size_t)(m0 + lr) * lda;
    const float* apr1 = Ag + (size_t)(m0 + lr + 64) * lda;

    auto store_sm = [&](int b2, float4 a0, float4 a1, float4 bb) {
        float* dA = sA + b2 * (BK * BM);
        dA[(lk4 + 0) * BM + lr] = a0.x;  dA[(lk4 + 1) * BM + lr] = a0.y;
        dA[(lk4 + 2) * BM + lr] = a0.z;  dA[(lk4 + 3) * BM + lr] = a0.w;
        dA[(lk4 + 0) * BM + lr + 64] = a1.x;  dA[(lk4 + 1) * BM + lr + 64] = a1.y;
        dA[(lk4 + 2) * BM + lr + 64] = a1.z;  dA[(lk4 + 3) * BM + lr + 64] = a1.w;
        float* dB = sB + b2 * (BK * BN);
        dB[(lk4 + 0) * BN + lr] = bb.x;  dB[(lk4 + 1) * BN + lr] = bb.y;
        dB[(lk4 + 2) * BN + lr] = bb.z;  dB[(lk4 + 3) * BN + lr] = bb.w;
    };

    float4 ra0 = *(const float4*)(apr0 + lk4);
    float4 ra1 = *(const float4*)(apr1 + lk4);
    float4 rb  = *(const float4*)(Bg + (size_t)(n0 + lr) * ldb + lk4);

    int buf = 0;
    store_sm(0, ra0, ra1, rb);
    __syncthreads();

    for (int s = 0; s < NSTEP; ++s) {
        float4 na0, na1, nb;
        if (s + 1 < NSTEP) {
            const int k0 = (s + 1) << 4;
            na0 = *(const float4*)(apr0 + k0 + lk4);
            na1 = *(const float4*)(apr1 + k0 + lk4);
            nb  = *(const float4*)(Bg + (size_t)(n0 + lr) * ldb + k0 + lk4);
        }
        const float* cA = sA + buf * (BK * BM) + r0;
        const float* cB = sB + buf * (BK * BN) + c0;
#pragma unroll
        for (int k = 0; k < BK; ++k) {
            float4 a0 = *(const float4*)(cA + k * BM);
            float4 a1 = *(const float4*)(cA + k * BM + 4);
            ull b0 = *(const ull*)(cB + k * BN);
            ull b1 = *(const ull*)(cB + k * BN + 2);
            ull p;
            p = pack2(a0.x); fma2(acc[0][0], p, b0); fma2(acc[0][1], p, b1);
            p = pack2(a0.y); fma2(acc[1][0], p, b0); fma2(acc[1][1], p, b1);
            p = pack2(a0.z); fma2(acc[2][0], p, b0); fma2(acc[2][1], p, b1);
            p = pack2(a0.w); fma2(acc[3][0], p, b0); fma2(acc[3][1], p, b1);
            p = pack2(a1.x); fma2(acc[4][0], p, b0); fma2(acc[4][1], p, b1);
            p = pack2(a1.y); fma2(acc[5][0], p, b0); fma2(acc[5][1], p, b1);
            p = pack2(a1.z); fma2(acc[6][0], p, b0); fma2(acc[6][1], p, b1);
            p = pack2(a1.w); fma2(acc[7][0], p, b0); fma2(acc[7][1], p, b1);
        }
        if (s + 1 < NSTEP) {
            store_sm(buf ^ 1, na0, na1, nb);
            __syncthreads();
            buf ^= 1;
        }
    }
    __syncthreads();
}

// ---------------- kernels ----------------
__global__ void k_init() { g_barrier = 0u; }

// fp16 Bm and Bm^T
__global__ void k_prep(const float* __restrict__ Bm) {
    const int idx = blockIdx.x * 256 + threadIdx.x;
    const __half h = __float2half_rn(Bm[idx]);
    g_BmH[idx] = h;
    const int i = idx >> 9, j = idx & 511;
    g_BmTH[j * NSd + i] = h;
}

// xA = x @ A^T + b   (exact fp32)
__global__ void __launch_bounds__(NTHREADS) k_xA(const float* __restrict__ x,
                                                 const float* __restrict__ A,
                                                 const float* __restrict__ b) {
    __shared__ float sA[2 * BK * BM];
    __shared__ float sB[2 * BK * BN];
    const int bid = blockIdx.x;
    const int m0 = (bid / TILES_NS) * BM;
    const int n0 = (bid % TILES_NS) * BN;
    ull acc[8][2];
#pragma unroll
    for (int i = 0; i < 8; ++i) { acc[i][0] = 0ull; acc[i][1] = 0ull; }
    gemm_tile_bt(x, NIN, A, NIN, m0, n0, NIN, acc, sA, sB);
    const int tid = threadIdx.x;
    const int r0 = (tid >> 4) * 8, c0 = (tid & 15) * 4;
    const float b0 = b[n0 + c0], b1 = b[n0 + c0 + 1], b2 = b[n0 + c0 + 2], b3 = b[n0 + c0 + 3];
#pragma unroll
    for (int r = 0; r < 8; ++r) {
        float2 lo = unpack2(acc[r][0]), hi = unpack2(acc[r][1]);
        float4 o = make_float4(lo.x + b0, lo.y + b1, hi.x + b2, hi.y + b3);
        *(float4*)&g_xA[(size_t)(m0 + r0 + r) * NSd + n0 + c0] = o;
    }
}

// Persistent fp16-tensor DEQ solver + g-phase + vjp; 512 threads.
__global__ void __launch_bounds__(NTH_IT, 1) k_iter(const float* __restrict__ v) {
    extern __shared__ __half smh[];
    __shared__ float red[NTH_IT];
    const uint32_t smb = smem_u32(smh);
    const int tid = threadIdx.x;
    const int w = tid >> 5, lane = tid & 31;
    const int wr = w >> 3, wc = w & 7;
    const int grp = lane >> 2, tg = lane & 3;
    const int m0 = blockIdx.x * 128;
    unsigned bar_exp = 0;
    int final_p = 0;
    float acc[4][4][4];

    for (int t = 1; t <= MAXITER; ++t) {
        const __half* zin = g_zh[t & 1];
        __half* zout = g_zh[(t - 1) & 1];
        float lnum = 0.f, lden = 0.f;

        if (t == 1) {
            // z1 = tanh(xA); res0 = 1 > eps always
            for (int i = tid; i < (128 * NSd) / 4; i += NTH_IT) {
                const size_t idx = (size_t)m0 * NSd + (size_t)i * 4;
                float4 xa = *(const float4*)&g_xA[idx];
                __half h0 = __float2half_rn(tanhf(xa.x));
                __half h1 = __float2half_rn(tanhf(xa.y));
                __half h2 = __float2half_rn(tanhf(xa.z));
                __half h3 = __float2half_rn(tanhf(xa.w));
                const float z0 = __half2float(h0), z1 = __half2float(h1);
                const float z2 = __half2float(h2), z3 = __half2float(h3);
                const float s = z0 * z0 + z1 * z1 + z2 * z2 + z3 * z3;
                lnum += s; lden += s;
                *(__half2*)&zout[idx]     = __halves2half2(h0, h1);
                *(__half2*)&zout[idx + 2] = __halves2half2(h2, h3);
            }
        } else {
            for (int nc = 0; nc < NPASS; ++nc) {
                mma_pass_f16(zin + (size_t)m0 * NSd, g_BmH + (size_t)nc * BROWS * NSd,
                             smb, acc);
#pragma unroll
                for (int f = 0; f < 4; ++f) {
                    const int m = m0 + wr * 64 + f * 16 + grp;
#pragma unroll
                    for (int g = 0; g < 4; ++g) {
                        const int n = nc * BROWS + wc * 32 + g * 8 + tg * 2;
#pragma unroll
                        for (int hr = 0; hr < 2; ++hr) {
                            const size_t idx = (size_t)(m + hr * 8) * NSd + n;
                            float2 xa = *(const float2*)&g_xA[idx];
                            __half hx = __float2half_rn(tanhf(xa.x + acc[f][g][hr * 2 + 0]));
                            __half hy = __float2half_rn(tanhf(xa.y + acc[f][g][hr * 2 + 1]));
                            const float zx = __half2float(hx), zy = __half2float(hy);
                            __half2 zp = *(const __half2*)&zin[idx];
                            const float dx = zx - __low2float(zp);
                            const float dy = zy - __high2float(zp);
                            lnum += dx * dx + dy * dy;
                            lden += zx * zx + zy * zy;
                            *(__half2*)&zout[idx] = __halves2half2(hx, hy);
                        }
                    }
                }
            }
        }

        float bnum = block_reduce512(lnum, red);
        float bden = block_reduce512(lden, red);
        if (tid == 0) {
            const int slot = t & 1;
            g_part[slot][2 * blockIdx.x]     = bnum;
            g_part[slot][2 * blockIdx.x + 1] = bden;
        }
        bar_exp += GRID_IT;
        grid_sync(bar_exp);

        // parallel decision: identical deterministic computation in every thread/CTA
        {
            const int slot = t & 1;
            float pn = 0.f, pd = 0.f;
            if (tid < GRID_IT) {
                pn = __ldcg(&g_part[slot][2 * tid]);
                pd = __ldcg(&g_part[slot][2 * tid + 1]);
            }
            float num = block_reduce512(pn, red);
            float den = block_reduce512(pd, red);
            const float res = sqrtf(num) / (sqrtf(den) + 1e-8f);
            if (res <= EPS_STOP || t == MAXITER) { final_p = (t - 1) & 1; break; }
        }
    }

    if (blockIdx.x == 0 && tid == 0) g_zparity = final_p;

    // g-phase: g = v * (1 - tanh(xA + z* @ Bm^T)^2)
    const __half* zs = g_zh[final_p];
    __half* gbuf = g_zh[final_p ^ 1];
    for (int nc = 0; nc < NPASS; ++nc) {
        mma_pass_f16(zs + (size_t)m0 * NSd, g_BmH + (size_t)nc * BROWS * NSd, smb, acc);
#pragma unroll
        for (int f = 0; f < 4; ++f) {
            const int m = m0 + wr * 64 + f * 16 + grp;
#pragma unroll
            for (int g = 0; g < 4; ++g) {
                const int n = nc * BROWS + wc * 32 + g * 8 + tg * 2;
#pragma unroll
                for (int hr = 0; hr < 2; ++hr) {
                    const size_t idx = (size_t)(m + hr * 8) * NSd + n;
                    float2 xa = *(const float2*)&g_xA[idx];
                    float2 vv = *(const float2*)&v[idx];
                    float th;
                    th = tanhf(xa.x + acc[f][g][hr * 2 + 0]);
                    __half gx = __float2half_rn(vv.x * (1.f - th * th));
                    th = tanhf(xa.y + acc[f][g][hr * 2 + 1]);
                    __half gy = __float2half_rn(vv.y * (1.f - th * th));
                    *(__half2*)&gbuf[idx] = __halves2half2(gx, gy);
                }
            }
        }
    }
    __threadfence();
    __syncthreads();

    // vjp: vJ = g @ Bm = g @ (BmT)^T ; sum of squares
    float ls = 0.f;
    for (int nc = 0; nc < NPASS; ++nc) {
        mma_pass_f16(gbuf + (size_t)m0 * NSd, g_BmTH + (size_t)nc * BROWS * NSd, smb, acc);
#pragma unroll
        for (int f = 0; f < 4; ++f)
#pragma unroll
            for (int g = 0; g < 4; ++g)
#pragma unroll
                for (int r = 0; r < 4; ++r)
                    ls += acc[f][g][r] * acc[f][g][r];
    }
    float bs = block_reduce512(ls, red);
    if (tid == 0) g_jacpart[blockIdx.x] = bs;
}

// z* fp16 -> fp32 for the exact y GEMM
__global__ void k_cvt() {
    const __half* zh = g_zh[g_zparity];
    const size_t i = ((size_t)blockIdx.x * 256 + threadIdx.x) * 4;
    __half2 p0 = *(const __half2*)&zh[i];
    __half2 p1 = *(const __half2*)&zh[i + 2];
    float4 o = make_float4(__low2float(p0), __high2float(p0),
                           __low2float(p1), __high2float(p1));
    *(float4*)&g_zf[i] = o;
}

// y = z* @ Wh^T + bh   (exact fp32 on fp16-rounded z*)
__global__ void __launch_bounds__(NTHREADS) k_y(const float* __restrict__ Wh,
                                                const float* __restrict__ bh,
                                                float* __restrict__ out) {
    __shared__ float sA[2 * BK * BM];
    __shared__ float sB[2 * BK * BN];
    const int m0 = blockIdx.x * BM;
    ull acc[8][2];
#pragma unroll
    for (int i = 0; i < 8; ++i) { acc[i][0] = 0ull; acc[i][1] = 0ull; }
    gemm_tile_bt(g_zf, NSd, Wh, NSd, m0, 0, NSd, acc, sA, sB);
    const int tid = threadIdx.x;
    const int r0 = (tid >> 4) * 8, c0 = (tid & 15) * 4;
    const float b0 = bh[c0], b1 = bh[c0 + 1], b2 = bh[c0 + 2], b3 = bh[c0 + 3];
#pragma unroll
    for (int r = 0; r < 8; ++r) {
        float2 lo = unpack2(acc[r][0]), hi = unpack2(acc[r][1]);
        float4 o = make_float4(lo.x + b0, lo.y + b1, hi.x + b2, hi.y + b3);
        *(float4*)&out[(size_t)(m0 + r0 + r) * NOUT + c0] = o;
    }
}

__global__ void k_jac(float* __restrict__ out) {
    __shared__ float sred[NTHREADS];
    const int tid = threadIdx.x;
    float s = (tid < GRID_IT) ? g_jacpart[tid] : 0.f;
    sred[tid] = s; __syncthreads();
    for (int o = 128; o > 0; o >>= 1) {
        if (tid < o) sred[tid] += sred[tid + o];
        __syncthreads();
    }
    if (tid == 0) out[(size_t)NM * NOUT] = sred[0] / ((float)NM * (float)NSd);
}

// ---------------- launcher ----------------
extern "C" void kernel_launch(void* const* d_in, const int* in_sizes, int n_in,
                              void* d_out, int out_size) {
    const float* x   = (const float*)d_in[0];
    const float* A   = (const float*)d_in[1];
    const float* Bm  = (const float*)d_in[2];
    const float* b   = (const float*)d_in[3];
    const float* Wh  = (const float*)d_in[4];
    const float* bh  = (const float*)d_in[5];
    const float* v   = (const float*)d_in[6];
    float* out = (float*)d_out;

    static int configured = 0;
    if (!configured) {
        cudaFuncSetAttribute(k_iter, cudaFuncAttributeMaxDynamicSharedMemorySize, SMEM_DYN);
        configured = 1;
    }

    k_init<<<1, 1>>>();
    k_prep<<<(NSd * NSd) / 256, 256>>>(Bm);
    k_xA<<<NTILES, NTHREADS>>>(x, A, b);
    k_iter<<<GRID_IT, NTH_IT, SMEM_DYN>>>(v);
    k_cvt<<<(NM * NSd) / (256 * 4), 256>>>();
    k_y<<<TILES_M, NTHREADS>>>(Wh, bh, out);
    k_jac<<<1, NTHREADS>>>(out);
}

// round 8
// speedup vs baseline: 4.6929x; 1.1977x over previous
#include <cuda_runtime.h>
#include <cuda_fp16.h>
#include <math.h>
#include <stdint.h>

typedef unsigned long long ull;

#define NM    16384
#define NSd   512
#define NIN   64
#define NOUT  64
#define BM    128
#define BN    64
#define BK    16
#define NTHREADS 256
#define TILES_M   (NM / BM)            // 128
#define TILES_NS  (NSd / BN)           // 8
#define NTILES    (TILES_M * TILES_NS) // 1024
#define MAXITER   200
#define EPS_STOP  1e-3f

// ---- fp16 mma path, z-resident-in-SMEM ----
#define GRID_IT   128                  // persistent CTAs, one M=128 tile each
#define NTH_IT    512                  // 16 warps
#define KC        64                   // K (halves) per B chunk
#define NCHUNK    8                    // 512 / 64
#define BROWS     256                  // B rows staged per pass (2 passes cover N=512)
#define LDH       72                   // B stage row pitch (halves) -> conflict-free ldmatrix
#define LDB       (LDH * 2)            // 144 B
#define BSTAGE    (BROWS * LDB)        // 36864 B per stage
#define Z_LDH     520                  // z row pitch in halves (512 + 8 pad) -> stride 1040 B
#define Z_BYTES   (128 * Z_LDH * 2)    // 133120 B
#define SMEM_DYN  (Z_BYTES + 2 * BSTAGE)   // 206848 B

// ---------------- device scratch ----------------
__device__ float  g_xA[NM * NSd];          // x@A^T + b (exact fp32)
__device__ float  g_zf[NM * NSd];          // fp32 z* for k_y
__device__ __half g_BmH[NSd * NSd];        // fp16 Bm  (rows = n, cols = k)
__device__ __half g_BmTH[NSd * NSd];       // fp16 Bm^T
__device__ unsigned g_barrier;
__device__ float g_part[2][2 * GRID_IT];
__device__ float g_jacpart[GRID_IT];

// ---------------- small helpers ----------------
__device__ __forceinline__ uint32_t smem_u32(const void* p) {
    uint32_t a;
    asm("{ .reg .u64 t; cvta.to.shared.u64 t, %1; cvt.u32.u64 %0, t; }" : "=r"(a) : "l"(p));
    return a;
}
__device__ __forceinline__ float tanh_ap(float x) {
    float y; asm("tanh.approx.f32 %0, %1;" : "=f"(y) : "f"(x)); return y;
}
__device__ __forceinline__ void cp_async16(uint32_t saddr, const void* g) {
    asm volatile("cp.async.cg.shared.global [%0], [%1], 16;" :: "r"(saddr), "l"(g) : "memory");
}
__device__ __forceinline__ void ldmatrix_x4(uint32_t r[4], uint32_t addr) {
    asm volatile("ldmatrix.sync.aligned.m8n8.x4.shared.b16 {%0,%1,%2,%3}, [%4];"
        : "=r"(r[0]), "=r"(r[1]), "=r"(r[2]), "=r"(r[3]) : "r"(addr));
}
__device__ __forceinline__ void mma_f16(float c[4], const uint32_t a[4], const uint32_t b[2]) {
    asm volatile(
        "mma.sync.aligned.m16n8k16.row.col.f32.f16.f16.f32 "
        "{%0,%1,%2,%3}, {%4,%5,%6,%7}, {%8,%9}, {%0,%1,%2,%3};"
        : "+f"(c[0]), "+f"(c[1]), "+f"(c[2]), "+f"(c[3])
        : "r"(a[0]), "r"(a[1]), "r"(a[2]), "r"(a[3]), "r"(b[0]), "r"(b[1]));
}

// ---------------- grid barrier (all CTAs resident: 128 <= #SMs) ----------------
__device__ __forceinline__ void grid_sync(unsigned expected) {
    __syncthreads();
    if (threadIdx.x == 0) {
        __threadfence();
        unsigned arr = atomicAdd(&g_barrier, 1u) + 1u;
        if (arr < expected) {
            while (*(volatile unsigned*)&g_barrier < expected) { }
        }
        __threadfence();
    }
    __syncthreads();
}

__device__ __forceinline__ float block_reduce512(float v, float* sred) {
    const int tid = threadIdx.x;
    sred[tid] = v; __syncthreads();
#pragma unroll
    for (int o = NTH_IT / 2; o > 0; o >>= 1) {
        if (tid < o) sred[tid] += sred[tid + o];
        __syncthreads();
    }
    float r = sred[0];
    __syncthreads();
    return r;
}

// ---------------- fp16 mma pass with A resident in SMEM ----------------
// acc[128x256] = Z(128x512, smem @ zb) @ Brows(256x512)^T; B double-buffered.
// Warp grid 2(M) x 8(N); warp tile 64x32; one __syncthreads per 64-k chunk.
__device__ void mma_passR(uint32_t zb, const __half* __restrict__ Brows,
                          uint32_t bb, float acc[4][4][4]) {
    const int tid = threadIdx.x;
    const int w = tid >> 5, lane = tid & 31;
    const int wr = w >> 3, wc = w & 7;

#pragma unroll
    for (int f = 0; f < 4; ++f)
#pragma unroll
        for (int g = 0; g < 4; ++g)
#pragma unroll
            for (int r = 0; r < 4; ++r) acc[f][g][r] = 0.f;

    __syncthreads();   // previous users of smem (B stages / z writes) done

    const int lrow = tid >> 3, lseg = tid & 7;   // B: 64 rows per i-step, 8 x 16B per row

    auto load_chunk = [&](int c, int stage) {
        const uint32_t sb = bb + (uint32_t)(stage * BSTAGE);
        const int k0 = c * KC;
#pragma unroll
        for (int i = 0; i < 4; ++i) {            // 256 rows x 8 segs / 512 thr = 4
            const int row = i * 64 + lrow;
            cp_async16(sb + (uint32_t)(row * LDB + lseg * 16),
                       Brows + (size_t)row * NSd + k0 + lseg * 8);
        }
        asm volatile("cp.async.commit_group;" ::: "memory");
    };

    load_chunk(0, 0);

    const int rsel = lane & 15;
    const int ksel = (lane >> 4) << 3;   // 0 or 8 halves
    const uint32_t zrow = zb + (uint32_t)((wr * 64 + rsel) * (Z_LDH * 2));

    for (int c = 0; c < NCHUNK; ++c) {
        asm volatile("cp.async.wait_group 0;" ::: "memory");
        __syncthreads();   // chunk c visible; prior chunk's stage free for refill

        if (c + 1 < NCHUNK) load_chunk(c + 1, (c + 1) & 1);

        const uint32_t sB = bb + (uint32_t)((c & 1) * BSTAGE);
#pragma unroll
        for (int ks = 0; ks < 4; ++ks) {
            const uint32_t koff = (uint32_t)((ks * 16 + ksel) * 2);
            const uint32_t akoff = (uint32_t)(c * (KC * 2)) + koff;
            uint32_t a[4][4], bf[2][4];
#pragma unroll
            for (int f = 0; f < 4; ++f)
                ldmatrix_x4(a[f], zrow + (uint32_t)(f * 16 * (Z_LDH * 2)) + akoff);
#pragma unroll
            for (int h = 0; h < 2; ++h)
                ldmatrix_x4(bf[h], sB + (uint32_t)((wc * 32 + h * 16 + rsel) * LDB) + koff);
#pragma unroll
            for (int f = 0; f < 4; ++f) {
                { uint32_t b2[2] = {bf[0][0], bf[0][2]}; mma_f16(acc[f][0], a[f], b2); }
                { uint32_t b2[2] = {bf[0][1], bf[0][3]}; mma_f16(acc[f][1], a[f], b2); }
                { uint32_t b2[2] = {bf[1][0], bf[1][2]}; mma_f16(acc[f][2], a[f], b2); }
                { uint32_t b2[2] = {bf[1][1], bf[1][3]}; mma_f16(acc[f][3], a[f], b2); }
            }
        }
    }
}

// ---------------- fp32 SGEMM (f32x2) — exact paths: xA and y ----------------
__device__ __forceinline__ ull pack2(float x) {
    ull r; unsigned u = __float_as_uint(x);
    asm("mov.b64 %0, {%1, %1};" : "=l"(r) : "r"(u));
    return r;
}
__device__ __forceinline__ void fma2(ull& d, ull a, ull b) {
    asm("fma.rn.f32x2 %0, %1, %2, %0;" : "+l"(d) : "l"(a), "l"(b));
}
__device__ __forceinline__ float2 unpack2(ull p) {
    unsigned lo, hi;
    asm("mov.b64 {%0, %1}, %2;" : "=r"(lo), "=r"(hi) : "l"(p));
    return make_float2(__uint_as_float(lo), __uint_as_float(hi));
}

__device__ __forceinline__ void gemm_tile_bt(
    const float* __restrict__ Ag, int lda,
    const float* __restrict__ Bg, int ldb,
    int m0, int n0, int K,
    ull acc[8][2], float* sA, float* sB) {
    const int tid = threadIdx.x;
    const int r0  = (tid >> 4) * 8;
    const int c0  = (tid & 15) * 4;
    const int lr  = tid >> 2;
    const int lk4 = (tid & 3) * 4;
    const int NSTEP = K >> 4;

    const float* apr0 = Ag + (size_t)(m0 + lr) * lda;
    const float* apr1 = Ag + (size_t)(m0 + lr + 64) * lda;

    auto store_sm = [&](int b2, float4 a0, float4 a1, float4 bb) {
        float* dA = sA + b2 * (BK * BM);
        dA[(lk4 + 0) * BM + lr] = a0.x;  dA[(lk4 + 1) * BM + lr] = a0.y;
        dA[(lk4 + 2) * BM + lr] = a0.z;  dA[(lk4 + 3) * BM + lr] = a0.w;
        dA[(lk4 + 0) * BM + lr + 64] = a1.x;  dA[(lk4 + 1) * BM + lr + 64] = a1.y;
        dA[(lk4 + 2) * BM + lr + 64] = a1.z;  dA[(lk4 + 3) * BM + lr + 64] = a1.w;
        float* dB = sB + b2 * (BK * BN);
        dB[(lk4 + 0) * BN + lr] = bb.x;  dB[(lk4 + 1) * BN + lr] = bb.y;
        dB[(lk4 + 2) * BN + lr] = bb.z;  dB[(lk4 + 3) * BN + lr] = bb.w;
    };

    float4 ra0 = *(const float4*)(apr0 + lk4);
    float4 ra1 = *(const float4*)(apr1 + lk4);
    float4 rb  = *(const float4*)(Bg + (size_t)(n0 + lr) * ldb + lk4);

    int buf = 0;
    store_sm(0, ra0, ra1, rb);
    __syncthreads();

    for (int s = 0; s < NSTEP; ++s) {
        float4 na0, na1, nb;
        if (s + 1 < NSTEP) {
            const int k0 = (s + 1) << 4;
            na0 = *(const float4*)(apr0 + k0 + lk4);
            na1 = *(const float4*)(apr1 + k0 + lk4);
            nb  = *(const float4*)(Bg + (size_t)(n0 + lr) * ldb + k0 + lk4);
        }
        const float* cA = sA + buf * (BK * BM) + r0;
        const float* cB = sB + buf * (BK * BN) + c0;
#pragma unroll
        for (int k = 0; k < BK; ++k) {
            float4 a0 = *(const float4*)(cA + k * BM);
            float4 a1 = *(const float4*)(cA + k * BM + 4);
            ull b0 = *(const ull*)(cB + k * BN);
            ull b1 = *(const ull*)(cB + k * BN + 2);
            ull p;
            p = pack2(a0.x); fma2(acc[0][0], p, b0); fma2(acc[0][1], p, b1);
            p = pack2(a0.y); fma2(acc[1][0], p, b0); fma2(acc[1][1], p, b1);
            p = pack2(a0.z); fma2(acc[2][0], p, b0); fma2(acc[2][1], p, b1);
            p = pack2(a0.w); fma2(acc[3][0], p, b0); fma2(acc[3][1], p, b1);
            p = pack2(a1.x); fma2(acc[4][0], p, b0); fma2(acc[4][1], p, b1);
            p = pack2(a1.y); fma2(acc[5][0], p, b0); fma2(acc[5][1], p, b1);
            p = pack2(a1.z); fma2(acc[6][0], p, b0); fma2(acc[6][1], p, b1);
            p = pack2(a1.w); fma2(acc[7][0], p, b0); fma2(acc[7][1], p, b1);
        }
        if (s + 1 < NSTEP) {
            store_sm(buf ^ 1, na0, na1, nb);
            __syncthreads();
            buf ^= 1;
        }
    }
    __syncthreads();
}

// ---------------- kernels ----------------
__global__ void k_init() { g_barrier = 0u; }

__global__ void k_prep(const float* __restrict__ Bm) {
    const int idx = blockIdx.x * 256 + threadIdx.x;
    const __half h = __float2half_rn(Bm[idx]);
    g_BmH[idx] = h;
    const int i = idx >> 9, j = idx & 511;
    g_BmTH[j * NSd + i] = h;
}

// xA = x @ A^T + b   (exact fp32)
__global__ void __launch_bounds__(NTHREADS) k_xA(const float* __restrict__ x,
                                                 const float* __restrict__ A,
                                                 const float* __restrict__ b) {
    __shared__ float sA[2 * BK * BM];
    __shared__ float sB[2 * BK * BN];
    const int bid = blockIdx.x;
    const int m0 = (bid / TILES_NS) * BM;
    const int n0 = (bid % TILES_NS) * BN;
    ull acc[8][2];
#pragma unroll
    for (int i = 0; i < 8; ++i) { acc[i][0] = 0ull; acc[i][1] = 0ull; }
    gemm_tile_bt(x, NIN, A, NIN, m0, n0, NIN, acc, sA, sB);
    const int tid = threadIdx.x;
    const int r0 = (tid >> 4) * 8, c0 = (tid & 15) * 4;
    const float b0 = b[n0 + c0], b1 = b[n0 + c0 + 1], b2 = b[n0 + c0 + 2], b3 = b[n0 + c0 + 3];
#pragma unroll
    for (int r = 0; r < 8; ++r) {
        float2 lo = unpack2(acc[r][0]), hi = unpack2(acc[r][1]);
        float4 o = make_float4(lo.x + b0, lo.y + b1, hi.x + b2, hi.y + b3);
        *(float4*)&g_xA[(size_t)(m0 + r0 + r) * NSd + n0 + c0] = o;
    }
}

// Persistent fp16-tensor DEQ solver (z resident in SMEM) + y-dump + g-phase + vjp.
__global__ void __launch_bounds__(NTH_IT, 1) k_iter(const float* __restrict__ v) {
    extern __shared__ __half smh[];
    __shared__ float red[NTH_IT];
    const uint32_t zb = smem_u32(smh);
    const uint32_t bb = zb + (uint32_t)Z_BYTES;
    const int tid = threadIdx.x;
    const int w = tid >> 5, lane = tid & 31;
    const int wr = w >> 3, wc = w & 7;
    const int grp = lane >> 2, tg = lane & 3;
    const int m0 = blockIdx.x * 128;
    unsigned bar_exp = 0;
    float acc[4][4][4];
    uint32_t stash[32];

    for (int t = 1; t <= MAXITER; ++t) {
        float lnum = 0.f, lden = 0.f;

        if (t == 1) {
            // z1 = tanh(xA) -> smem; res0 = 1 > eps always
            for (int i = tid; i < (128 * NSd) / 4; i += NTH_IT) {
                const int row = (i * 4) >> 9, col = (i * 4) & 511;
                float4 xa = *(const float4*)&g_xA[(size_t)(m0 + row) * NSd + col];
                __half h0 = __float2half_rn(tanh_ap(xa.x));
                __half h1 = __float2half_rn(tanh_ap(xa.y));
                __half h2 = __float2half_rn(tanh_ap(xa.z));
                __half h3 = __float2half_rn(tanh_ap(xa.w));
                const float z0 = __half2float(h0), z1 = __half2float(h1);
                const float z2 = __half2float(h2), z3 = __half2float(h3);
                const float s = z0 * z0 + z1 * z1 + z2 * z2 + z3 * z3;
                lnum += s; lden += s;
                *(__half2*)&smh[row * Z_LDH + col]     = __halves2half2(h0, h1);
                *(__half2*)&smh[row * Z_LDH + col + 2] = __halves2half2(h2, h3);
            }
        } else {
            // pass 0: cols 0-255; stash results in registers (zin smem must stay intact)
            mma_passR(zb, g_BmH, bb, acc);
#pragma unroll
            for (int f = 0; f < 4; ++f) {
                const int mloc = wr * 64 + f * 16 + grp;
#pragma unroll
                for (int g = 0; g < 4; ++g) {
                    const int n = wc * 32 + g * 8 + tg * 2;
#pragma unroll
                    for (int hr = 0; hr < 2; ++hr) {
                        const int ml = mloc + hr * 8;
                        float2 xa = *(const float2*)&g_xA[(size_t)(m0 + ml) * NSd + n];
                        __half hx = __float2half_rn(tanh_ap(xa.x + acc[f][g][hr * 2 + 0]));
                        __half hy = __float2half_rn(tanh_ap(xa.y + acc[f][g][hr * 2 + 1]));
                        const float zx = __half2float(hx), zy = __half2float(hy);
                        __half2 zp = *(__half2*)&smh[ml * Z_LDH + n];
                        const float dx = zx - __low2float(zp);
                        const float dy = zy - __high2float(zp);
                        lnum += dx * dx + dy * dy;
                        lden += zx * zx + zy * zy;
                        __half2 hh = __halves2half2(hx, hy);
                        stash[(f * 4 + g) * 2 + hr] = *reinterpret_cast<uint32_t*>(&hh);
                    }
                }
            }
            // pass 1: cols 256-511
            mma_passR(zb, g_BmH + (size_t)256 * NSd, bb, acc);
            __syncthreads();   // all GEMM1 reads of z done -> safe to overwrite
#pragma unroll
            for (int f = 0; f < 4; ++f) {
                const int mloc = wr * 64 + f * 16 + grp;
#pragma unroll
                for (int g = 0; g < 4; ++g) {
                    const int n = wc * 32 + g * 8 + tg * 2;
#pragma unroll
                    for (int hr = 0; hr < 2; ++hr) {
                        const int ml = mloc + hr * 8;
                        const int n2 = 256 + n;
                        float2 xa = *(const float2*)&g_xA[(size_t)(m0 + ml) * NSd + n2];
                        __half hx = __float2half_rn(tanh_ap(xa.x + acc[f][g][hr * 2 + 0]));
                        __half hy = __float2half_rn(tanh_ap(xa.y + acc[f][g][hr * 2 + 1]));
                        const float zx = __half2float(hx), zy = __half2float(hy);
                        __half2 zp = *(__half2*)&smh[ml * Z_LDH + n2];
                        const float dx = zx - __low2float(zp);
                        const float dy = zy - __high2float(zp);
                        lnum += dx * dx + dy * dy;
                        lden += zx * zx + zy * zy;
                        *(__half2*)&smh[ml * Z_LDH + n2] = __halves2half2(hx, hy);
                        *(__half2*)&smh[ml * Z_LDH + n] =
                            *reinterpret_cast<__half2*>(&stash[(f * 4 + g) * 2 + hr]);
                    }
                }
            }
        }

        float bnum = block_reduce512(lnum, red);
        float bden = block_reduce512(lden, red);
        if (tid == 0) {
            const int slot = t & 1;
            g_part[slot][2 * blockIdx.x]     = bnum;
            g_part[slot][2 * blockIdx.x + 1] = bden;
        }
        bar_exp += GRID_IT;
        grid_sync(bar_exp);

        {
            const int slot = t & 1;
            float pn = 0.f, pd = 0.f;
            if (tid < GRID_IT) {
                pn = __ldcg(&g_part[slot][2 * tid]);
                pd = __ldcg(&g_part[slot][2 * tid + 1]);
            }
            float num = block_reduce512(pn, red);
            float den = block_reduce512(pd, red);
            const float res = sqrtf(num) / (sqrtf(den) + 1e-8f);
            if (res <= EPS_STOP || t == MAXITER) break;
        }
    }

    // dump z* fp32 to gmem for k_y (z* lives in smem)
    for (int i = tid; i < (128 * NSd) / 4; i += NTH_IT) {
        const int row = (i * 4) >> 9, col = (i * 4) & 511;
        __half2 p0 = *(__half2*)&smh[row * Z_LDH + col];
        __half2 p1 = *(__half2*)&smh[row * Z_LDH + col + 2];
        *(float4*)&g_zf[(size_t)(m0 + row) * NSd + col] =
            make_float4(__low2float(p0), __high2float(p0),
                        __low2float(p1), __high2float(p1));
    }

    // g-phase: g = v * (1 - tanh(xA + z* @ Bm^T)^2); g overwrites z in smem
    mma_passR(zb, g_BmH, bb, acc);
#pragma unroll
    for (int f = 0; f < 4; ++f) {
        const int mloc = wr * 64 + f * 16 + grp;
#pragma unroll
        for (int g = 0; g < 4; ++g) {
            const int n = wc * 32 + g * 8 + tg * 2;
#pragma unroll
            for (int hr = 0; hr < 2; ++hr) {
                const int ml = mloc + hr * 8;
                float2 xa = *(const float2*)&g_xA[(size_t)(m0 + ml) * NSd + n];
                float2 vv = *(const float2*)&v[(size_t)(m0 + ml) * NSd + n];
                float th;
                th = tanh_ap(xa.x + acc[f][g][hr * 2 + 0]);
                __half gx = __float2half_rn(vv.x * (1.f - th * th));
                th = tanh_ap(xa.y + acc[f][g][hr * 2 + 1]);
                __half gy = __float2half_rn(vv.y * (1.f - th * th));
                __half2 hh = __halves2half2(gx, gy);
                stash[(f * 4 + g) * 2 + hr] = *reinterpret_cast<uint32_t*>(&hh);
            }
        }
    }
    mma_passR(zb, g_BmH + (size_t)256 * NSd, bb, acc);
    __syncthreads();
#pragma unroll
    for (int f = 0; f < 4; ++f) {
        const int mloc = wr * 64 + f * 16 + grp;
#pragma unroll
        for (int g = 0; g < 4; ++g) {
            const int n = wc * 32 + g * 8 + tg * 2;
#pragma unroll
            for (int hr = 0; hr < 2; ++hr) {
                const int ml = mloc + hr * 8;
                const int n2 = 256 + n;
                float2 xa = *(const float2*)&g_xA[(size_t)(m0 + ml) * NSd + n2];
                float2 vv = *(const float2*)&v[(size_t)(m0 + ml) * NSd + n2];
                float th;
                th = tanh_ap(xa.x + acc[f][g][hr * 2 + 0]);
                __half gx = __float2half_rn(vv.x * (1.f - th * th));
                th = tanh_ap(xa.y + acc[f][g][hr * 2 + 1]);
                __half gy = __float2half_rn(vv.y * (1.f - th * th));
                *(__half2*)&smh[ml * Z_LDH + n2] = __halves2half2(gx, gy);
                *(__half2*)&smh[ml * Z_LDH + n] =
                    *reinterpret_cast<__half2*>(&stash[(f * 4 + g) * 2 + hr]);
            }
        }
    }

    // vjp: vJ = g @ Bm = g @ (BmT)^T ; sum of squares (no writes)
    float ls = 0.f;
    mma_passR(zb, g_BmTH, bb, acc);
#pragma unroll
    for (int f = 0; f < 4; ++f)
#pragma unroll
        for (int g = 0; g < 4; ++g)
#pragma unroll
            for (int r = 0; r < 4; ++r) ls += acc[f][g][r] * acc[f][g][r];
    mma_passR(zb, g_BmTH + (size_t)256 * NSd, bb, acc);
#pragma unroll
    for (int f = 0; f < 4; ++f)
#pragma unroll
        for (int g = 0; g < 4; ++g)
#pragma unroll
            for (int r = 0; r < 4; ++r) ls += acc[f][g][r] * acc[f][g][r];

    float bs = block_reduce512(ls, red);
    if (tid == 0) g_jacpart[blockIdx.x] = bs;
}

// y = z* @ Wh^T + bh   (exact fp32 on fp16-rounded z*)
__global__ void __launch_bounds__(NTHREADS) k_y(const float* __restrict__ Wh,
                                                const float* __restrict__ bh,
                                                float* __restrict__ out) {
    __shared__ float sA[2 * BK * BM];
    __shared__ float sB[2 * BK * BN];
    const int m0 = blockIdx.x * BM;
    ull acc[8][2];
#pragma unroll
    for (int i = 0; i < 8; ++i) { acc[i][0] = 0ull; acc[i][1] = 0ull; }
    gemm_tile_bt(g_zf, NSd, Wh, NSd, m0, 0, NSd, acc, sA, sB);
    const int tid = threadIdx.x;
    const int r0 = (tid >> 4) * 8, c0 = (tid & 15) * 4;
    const float b0 = bh[c0], b1 = bh[c0 + 1], b2 = bh[c0 + 2], b3 = bh[c0 + 3];
#pragma unroll
    for (int r = 0; r < 8; ++r) {
        float2 lo = unpack2(acc[r][0]), hi = unpack2(acc[r][1]);
        float4 o = make_float4(lo.x + b0, lo.y + b1, hi.x + b2, hi.y + b3);
        *(float4*)&out[(size_t)(m0 + r0 + r) * NOUT + c0] = o;
    }
}

__global__ void k_jac(float* __restrict__ out) {
    __shared__ float sred[NTHREADS];
    const int tid = threadIdx.x;
    float s = (tid < GRID_IT) ? g_jacpart[tid] : 0.f;
    sred[tid] = s; __syncthreads();
    for (int o = 128; o > 0; o >>= 1) {
        if (tid < o) sred[tid] += sred[tid + o];
        __syncthreads();
    }
    if (tid == 0) out[(size_t)NM * NOUT] = sred[0] / ((float)NM * (float)NSd);
}

// ---------------- launcher ----------------
extern "C" void kernel_launch(void* const* d_in, const int* in_sizes, int n_in,
                              void* d_out, int out_size) {
    const float* x   = (const float*)d_in[0];
    const float* A   = (const float*)d_in[1];
    const float* Bm  = (const float*)d_in[2];
    const float* b   = (const float*)d_in[3];
    const float* Wh  = (const float*)d_in[4];
    const float* bh  = (const float*)d_in[5];
    const float* v   = (const float*)d_in[6];
    float* out = (float*)d_out;

    static int configured = 0;
    if (!configured) {
        cudaFuncSetAttribute(k_iter, cudaFuncAttributeMaxDynamicSharedMemorySize, SMEM_DYN);
        configured = 1;
    }

    k_init<<<1, 1>>>();
    k_prep<<<(NSd * NSd) / 256, 256>>>(Bm);
    k_xA<<<NTILES, NTHREADS>>>(x, A, b);
    k_iter<<<GRID_IT, NTH_IT, SMEM_DYN>>>(v);
    k_y<<<TILES_M, NTHREADS>>>(Wh, bh, out);
    k_jac<<<1, NTHREADS>>>(out);
}

// round 9
// speedup vs baseline: 5.2081x; 1.1098x over previous
#include <cuda_runtime.h>
#include <cuda_fp16.h>
#include <math.h>
#include <stdint.h>

typedef unsigned long long ull;

#define NM    16384
#define NSd   512
#define NIN   64
#define NOUT  64
#define BM    128
#define BN    64
#define BK    16
#define NTHREADS 256
#define TILES_M   (NM / BM)            // 128
#define MAXITER   200
#define EPS_STOP  1e-3f

// ---- fp16 mma path, z-resident-in-SMEM ----
#define GRID_IT   128
#define NTH_IT    512                  // 16 warps
#define KC        64                   // K (halves) per B chunk
#define NCHUNK    8                    // 512 / 64
#define BROWS     256                  // B rows staged per pass
#define LDH       72                   // B stage row pitch (halves)
#define LDB       (LDH * 2)            // 144 B
#define BSTAGE    (BROWS * LDB)        // 36864 B per stage
#define Z_LDH     520                  // z row pitch halves
#define Z_BYTES   (128 * Z_LDH * 2)    // 133120 B
#define SMEM_DYN  (Z_BYTES + 2 * BSTAGE)   // 206848 B

// ---------------- device scratch ----------------
__device__ float  g_xA[NM * NSd];          // x@A^T + b (fp32 store)
__device__ float  g_zf[NM * NSd];          // fp32 z* for k_y
__device__ __half g_xH[NM * NIN];          // fp16 x
__device__ __half g_AH[NSd * NIN];         // fp16 A (rows n, cols k)
__device__ __half g_BmH[NSd * NSd];        // fp16 Bm  (rows n, cols k)
__device__ __half g_BmTH[NSd * NSd];       // fp16 Bm^T
__device__ unsigned g_barrier;
__device__ float g_part[2][2 * GRID_IT];
__device__ float g_jacpart[GRID_IT];

// ---------------- helpers ----------------
__device__ __forceinline__ uint32_t smem_u32(const void* p) {
    uint32_t a;
    asm("{ .reg .u64 t; cvta.to.shared.u64 t, %1; cvt.u32.u64 %0, t; }" : "=r"(a) : "l"(p));
    return a;
}
__device__ __forceinline__ float tanh_ap(float x) {
    float y; asm("tanh.approx.f32 %0, %1;" : "=f"(y) : "f"(x)); return y;
}
__device__ __forceinline__ void cp_async16(uint32_t saddr, const void* g) {
    asm volatile("cp.async.cg.shared.global [%0], [%1], 16;" :: "r"(saddr), "l"(g) : "memory");
}
__device__ __forceinline__ void ldmatrix_x4(uint32_t r[4], uint32_t addr) {
    asm volatile("ldmatrix.sync.aligned.m8n8.x4.shared.b16 {%0,%1,%2,%3}, [%4];"
        : "=r"(r[0]), "=r"(r[1]), "=r"(r[2]), "=r"(r[3]) : "r"(addr));
}
__device__ __forceinline__ void mma_f16(float c[4], const uint32_t a[4], const uint32_t b[2]) {
    asm volatile(
        "mma.sync.aligned.m16n8k16.row.col.f32.f16.f16.f32 "
        "{%0,%1,%2,%3}, {%4,%5,%6,%7}, {%8,%9}, {%0,%1,%2,%3};"
        : "+f"(c[0]), "+f"(c[1]), "+f"(c[2]), "+f"(c[3])
        : "r"(a[0]), "r"(a[1]), "r"(a[2]), "r"(a[3]), "r"(b[0]), "r"(b[1]));
}

// ---------------- grid barrier ----------------
__device__ __forceinline__ void grid_sync(unsigned expected) {
    __syncthreads();
    if (threadIdx.x == 0) {
        __threadfence();
        unsigned arr = atomicAdd(&g_barrier, 1u) + 1u;
        if (arr < expected) {
            while (*(volatile unsigned*)&g_barrier < expected) { }
        }
        __threadfence();
    }
    __syncthreads();
}

// Fused deterministic block reduce of two floats: shuffle butterfly + 16-partial
// fixed-order broadcast. 2 barriers. Identical result in every thread.
__device__ __forceinline__ float2 block_reduce2(float a, float b) {
    __shared__ float2 sr[16];
#pragma unroll
    for (int o = 16; o > 0; o >>= 1) {
        a += __shfl_xor_sync(0xFFFFFFFFu, a, o);
        b += __shfl_xor_sync(0xFFFFFFFFu, b, o);
    }
    const int w = threadIdx.x >> 5, lane = threadIdx.x & 31;
    __syncthreads();                     // protect sr from previous call's readers
    if (lane == 0) sr[w] = make_float2(a, b);
    __syncthreads();
    float2 t = make_float2(0.f, 0.f);
#pragma unroll
    for (int i = 0; i < 16; ++i) { t.x += sr[i].x; t.y += sr[i].y; }
    return t;
}

// ---------------- fp16 mma pass, A-operand resident in SMEM ----------------
// acc[128x256] = Aop(128 x NC*64, smem @ aBase, pitch aPitchB) @ Brows(256 x NC*64)^T
// Brows row stride bStrideH halves. B double-buffered via cp.async.
template<int NC>
__device__ void mma_pass(uint32_t aBase, int aPitchB,
                         const __half* __restrict__ Brows, int bStrideH,
                         uint32_t bb, float acc[4][4][4]) {
    const int tid = threadIdx.x;
    const int w = tid >> 5, lane = tid & 31;
    const int wr = w >> 3, wc = w & 7;

#pragma unroll
    for (int f = 0; f < 4; ++f)
#pragma unroll
        for (int g = 0; g < 4; ++g)
#pragma unroll
            for (int r = 0; r < 4; ++r) acc[f][g][r] = 0.f;

    __syncthreads();   // previous users of smem done

    const int lrow = tid >> 3, lseg = tid & 7;

    auto load_chunk = [&](int c, int stage) {
        const uint32_t sb = bb + (uint32_t)(stage * BSTAGE);
        const int k0 = c * KC;
#pragma unroll
        for (int i = 0; i < 4; ++i) {
            const int row = i * 64 + lrow;
            cp_async16(sb + (uint32_t)(row * LDB + lseg * 16),
                       Brows + (size_t)row * bStrideH + k0 + lseg * 8);
        }
        asm volatile("cp.async.commit_group;" ::: "memory");
    };

    load_chunk(0, 0);

    const int rsel = lane & 15;
    const int ksel = (lane >> 4) << 3;
    const uint32_t arow = aBase + (uint32_t)((wr * 64 + rsel) * aPitchB);

    for (int c = 0; c < NC; ++c) {
        asm volatile("cp.async.wait_group 0;" ::: "memory");
        __syncthreads();
        if (c + 1 < NC) load_chunk(c + 1, (c + 1) & 1);

        const uint32_t sB = bb + (uint32_t)((c & 1) * BSTAGE);
#pragma unroll
        for (int ks = 0; ks < 4; ++ks) {
            const uint32_t koff = (uint32_t)((ks * 16 + ksel) * 2);
            const uint32_t akoff = (uint32_t)(c * (KC * 2)) + koff;
            uint32_t a[4][4], bf[2][4];
#pragma unroll
            for (int f = 0; f < 4; ++f)
                ldmatrix_x4(a[f], arow + (uint32_t)(f * 16 * aPitchB) + akoff);
#pragma unroll
            for (int h = 0; h < 2; ++h)
                ldmatrix_x4(bf[h], sB + (uint32_t)((wc * 32 + h * 16 + rsel) * LDB) + koff);
#pragma unroll
            for (int f = 0; f < 4; ++f) {
                { uint32_t b2[2] = {bf[0][0], bf[0][2]}; mma_f16(acc[f][0], a[f], b2); }
                { uint32_t b2[2] = {bf[0][1], bf[0][3]}; mma_f16(acc[f][1], a[f], b2); }
                { uint32_t b2[2] = {bf[1][0], bf[1][2]}; mma_f16(acc[f][2], a[f], b2); }
                { uint32_t b2[2] = {bf[1][1], bf[1][3]}; mma_f16(acc[f][3], a[f], b2); }
            }
        }
    }
}

// ---------------- fp32 SGEMM (f32x2) — exact path for y ----------------
__device__ __forceinline__ ull pack2(float x) {
    ull r; unsigned u = __float_as_uint(x);
    asm("mov.b64 %0, {%1, %1};" : "=l"(r) : "r"(u));
    return r;
}
__device__ __forceinline__ void fma2(ull& d, ull a, ull b) {
    asm("fma.rn.f32x2 %0, %1, %2, %0;" : "+l"(d) : "l"(a), "l"(b));
}
__device__ __forceinline__ float2 unpack2(ull p) {
    unsigned lo, hi;
    asm("mov.b64 {%0, %1}, %2;" : "=r"(lo), "=r"(hi) : "l"(p));
    return make_float2(__uint_as_float(lo), __uint_as_float(hi));
}

__device__ __forceinline__ void gemm_tile_bt(
    const float* __restrict__ Ag, int lda,
    const float* __restrict__ Bg, int ldb,
    int m0, int n0, int K,
    ull acc[8][2], float* sA, float* sB) {
    const int tid = threadIdx.x;
    const int r0  = (tid >> 4) * 8;
    const int c0  = (tid & 15) * 4;
    const int lr  = tid >> 2;
    const int lk4 = (tid & 3) * 4;
    const int NSTEP = K >> 4;

    const float* apr0 = Ag + (size_t)(m0 + lr) * lda;
    const float* apr1 = Ag + (size_t)(m0 + lr + 64) * lda;

    auto store_sm = [&](int b2, float4 a0, float4 a1, float4 bb) {
        float* dA = sA + b2 * (BK * BM);
        dA[(lk4 + 0) * BM + lr] = a0.x;  dA[(lk4 + 1) * BM + lr] = a0.y;
        dA[(lk4 + 2) * BM + lr] = a0.z;  dA[(lk4 + 3) * BM + lr] = a0.w;
        dA[(lk4 + 0) * BM + lr + 64] = a1.x;  dA[(lk4 + 1) * BM + lr + 64] = a1.y;
        dA[(lk4 + 2) * BM + lr + 64] = a1.z;  dA[(lk4 + 3) * BM + lr + 64] = a1.w;
        float* dB = sB + b2 * (BK * BN);
        dB[(lk4 + 0) * BN + lr] = bb.x;  dB[(lk4 + 1) * BN + lr] = bb.y;
        dB[(lk4 + 2) * BN + lr] = bb.z;  dB[(lk4 + 3) * BN + lr] = bb.w;
    };

    float4 ra0 = *(const float4*)(apr0 + lk4);
    float4 ra1 = *(const float4*)(apr1 + lk4);
    float4 rb  = *(const float4*)(Bg + (size_t)(n0 + lr) * ldb + lk4);

    int buf = 0;
    store_sm(0, ra0, ra1, rb);
    __syncthreads();

    for (int s = 0; s < NSTEP; ++s) {
        float4 na0, na1, nb;
        if (s + 1 < NSTEP) {
            const int k0 = (s + 1) << 4;
            na0 = *(const float4*)(apr0 + k0 + lk4);
            na1 = *(const float4*)(apr1 + k0 + lk4);
            nb  = *(const float4*)(Bg + (size_t)(n0 + lr) * ldb + k0 + lk4);
        }
        const float* cA = sA + buf * (BK * BM) + r0;
        const float* cB = sB + buf * (BK * BN) + c0;
#pragma unroll
        for (int k = 0; k < BK; ++k) {
            float4 a0 = *(const float4*)(cA + k * BM);
            float4 a1 = *(const float4*)(cA + k * BM + 4);
            ull b0 = *(const ull*)(cB + k * BN);
            ull b1 = *(const ull*)(cB + k * BN + 2);
            ull p;
            p = pack2(a0.x); fma2(acc[0][0], p, b0); fma2(acc[0][1], p, b1);
            p = pack2(a0.y); fma2(acc[1][0], p, b0); fma2(acc[1][1], p, b1);
            p = pack2(a0.z); fma2(acc[2][0], p, b0); fma2(acc[2][1], p, b1);
            p = pack2(a0.w); fma2(acc[3][0], p, b0); fma2(acc[3][1], p, b1);
            p = pack2(a1.x); fma2(acc[4][0], p, b0); fma2(acc[4][1], p, b1);
            p = pack2(a1.y); fma2(acc[5][0], p, b0); fma2(acc[5][1], p, b1);
            p = pack2(a1.z); fma2(acc[6][0], p, b0); fma2(acc[6][1], p, b1);
            p = pack2(a1.w); fma2(acc[7][0], p, b0); fma2(acc[7][1], p, b1);
        }
        if (s + 1 < NSTEP) {
            store_sm(buf ^ 1, na0, na1, nb);
            __syncthreads();
            buf ^= 1;
        }
    }
    __syncthreads();
}

// ---------------- kernels ----------------
// All input conversions + barrier init. grid 2048 x 256.
__global__ void k_prep(const float* __restrict__ x,
                       const float* __restrict__ Bm,
                       const float* __restrict__ A) {
    const int gid = blockIdx.x * 256 + threadIdx.x;   // 0..524287
    float2 xv = *(const float2*)&x[(size_t)gid * 2];
    *(__half2*)&g_xH[(size_t)gid * 2] = __floats2half2_rn(xv.x, xv.y);
    if (gid < NSd * NSd) {
        const __half h = __float2half_rn(Bm[gid]);
        g_BmH[gid] = h;
        const int i = gid >> 9, j = gid & 511;
        g_BmTH[j * NSd + i] = h;
    }
    if (gid < NSd * NIN) g_AH[gid] = __float2half_rn(A[gid]);
    if (gid == 0) g_barrier = 0u;
}

// Persistent solver: fused xA (fp16 mma) + t=1, iterations, z* dump, g-phase, vjp.
__global__ void __launch_bounds__(NTH_IT, 1) k_iter(const float* __restrict__ bvec,
                                                    const float* __restrict__ v) {
    extern __shared__ __half smh[];
    const uint32_t zb = smem_u32(smh);
    const uint32_t bb = zb + (uint32_t)Z_BYTES;
    const int tid = threadIdx.x;
    const int w = tid >> 5, lane = tid & 31;
    const int wr = w >> 3, wc = w & 7;
    const int grp = lane >> 2, tg = lane & 3;
    const int m0 = blockIdx.x * 128;
    unsigned bar_exp = 0;
    float acc[4][4][4];
    uint32_t stash[32];

    // hoisted epilogue bases
    const int mbase = wr * 64 + grp;                       // local row base
    const float* xaRow = g_xA + (size_t)(m0 + mbase) * NSd;
    const float* vRow  = v    + (size_t)(m0 + mbase) * NSd;

    // ---- xA phase: load x-tile (128x64 fp16) into spare B-stage-1 area ----
    {
        const uint32_t xb = bb + (uint32_t)BSTAGE;
        for (int o = tid; o < 1024; o += NTH_IT) {
            const int row = o >> 3, seg = o & 7;
            cp_async16(xb + (uint32_t)(row * LDB + seg * 16),
                       g_xH + (size_t)(m0 + row) * NIN + seg * 8);
        }
        asm volatile("cp.async.commit_group;" ::: "memory");

        float lnum = 0.f;
#pragma unroll
        for (int pass = 0; pass < 2; ++pass) {
            mma_pass<1>(xb, LDB, g_AH + (size_t)pass * BROWS * NIN, NIN, bb, acc);
            const int n0 = pass * 256;
#pragma unroll
            for (int f = 0; f < 4; ++f) {
#pragma unroll
                for (int g = 0; g < 4; ++g) {
                    const int n = wc * 32 + g * 8 + tg * 2;
                    float2 bb2 = *(const float2*)&bvec[n0 + n];
#pragma unroll
                    for (int hr = 0; hr < 2; ++hr) {
                        const int ml = mbase + f * 16 + hr * 8;
                        const int off = (f * 16 + hr * 8) * NSd + n0 + n;
                        float xx = acc[f][g][hr * 2 + 0] + bb2.x;
                        float xy = acc[f][g][hr * 2 + 1] + bb2.y;
                        *(float2*)&((float*)xaRow)[off] = make_float2(xx, xy);
                        __half hx = __float2half_rn(tanh_ap(xx));
                        __half hy = __float2half_rn(tanh_ap(xy));
                        const float zx = __half2float(hx), zy = __half2float(hy);
                        lnum += zx * zx + zy * zy;
                        *(__half2*)&smh[ml * Z_LDH + n0 + n] = __halves2half2(hx, hy);
                    }
                }
            }
        }
        (void)lnum;   // res0 = 1 > eps always; no global round needed at t=1
    }

    // ---- iterations t = 2..MAXITER ----
    for (int t = 2; t <= MAXITER; ++t) {
        float lnum = 0.f, lden = 0.f;

        // pass 0: cols 0-255; stash (zin smem must stay intact for pass 1)
        mma_pass<NCHUNK>(zb, Z_LDH * 2, g_BmH, NSd, bb, acc);
#pragma unroll
        for (int f = 0; f < 4; ++f) {
#pragma unroll
            for (int g = 0; g < 4; ++g) {
                const int n = wc * 32 + g * 8 + tg * 2;
#pragma unroll
                for (int hr = 0; hr < 2; ++hr) {
                    const int ml = mbase + f * 16 + hr * 8;
                    float2 xa = *(const float2*)&xaRow[(f * 16 + hr * 8) * NSd + n];
                    __half hx = __float2half_rn(tanh_ap(xa.x + acc[f][g][hr * 2 + 0]));
                    __half hy = __float2half_rn(tanh_ap(xa.y + acc[f][g][hr * 2 + 1]));
                    const float zx = __half2float(hx), zy = __half2float(hy);
                    __half2 zp = *(__half2*)&smh[ml * Z_LDH + n];
                    const float dx = zx - __low2float(zp);
                    const float dy = zy - __high2float(zp);
                    lnum += dx * dx + dy * dy;
                    lden += zx * zx + zy * zy;
                    __half2 hh = __halves2half2(hx, hy);
                    stash[(f * 4 + g) * 2 + hr] = *reinterpret_cast<uint32_t*>(&hh);
                }
            }
        }
        // pass 1: cols 256-511
        mma_pass<NCHUNK>(zb, Z_LDH * 2, g_BmH + (size_t)256 * NSd, NSd, bb, acc);
        __syncthreads();   // all GEMM1 reads of z done -> safe to overwrite
#pragma unroll
        for (int f = 0; f < 4; ++f) {
#pragma unroll
            for (int g = 0; g < 4; ++g) {
                const int n = wc * 32 + g * 8 + tg * 2;
#pragma unroll
                for (int hr = 0; hr < 2; ++hr) {
                    const int ml = mbase + f * 16 + hr * 8;
                    const int n2 = 256 + n;
                    float2 xa = *(const float2*)&xaRow[(f * 16 + hr * 8) * NSd + n2];
                    __half hx = __float2half_rn(tanh_ap(xa.x + acc[f][g][hr * 2 + 0]));
                    __half hy = __float2half_rn(tanh_ap(xa.y + acc[f][g][hr * 2 + 1]));
                    const float zx = __half2float(hx), zy = __half2float(hy);
                    __half2 zp = *(__half2*)&smh[ml * Z_LDH + n2];
                    const float dx = zx - __low2float(zp);
                    const float dy = zy - __high2float(zp);
                    lnum += dx * dx + dy * dy;
                    lden += zx * zx + zy * zy;
                    *(__half2*)&smh[ml * Z_LDH + n2] = __halves2half2(hx, hy);
                    *(__half2*)&smh[ml * Z_LDH + n] =
                        *reinterpret_cast<__half2*>(&stash[(f * 4 + g) * 2 + hr]);
                }
            }
        }

        float2 bpart = block_reduce2(lnum, lden);
        if (tid == 0) {
            const int slot = t & 1;
            g_part[slot][2 * blockIdx.x]     = bpart.x;
            g_part[slot][2 * blockIdx.x + 1] = bpart.y;
        }
        bar_exp += GRID_IT;
        grid_sync(bar_exp);

        {
            const int slot = t & 1;
            float pn = 0.f, pd = 0.f;
            if (tid < GRID_IT) {
                float2 pp = __ldcg((const float2*)&g_part[slot][2 * tid]);
                pn = pp.x; pd = pp.y;
            }
            float2 tot = block_reduce2(pn, pd);
            const float res = sqrtf(tot.x) / (sqrtf(tot.y) + 1e-8f);
            if (res <= EPS_STOP || t == MAXITER) break;
        }
    }

    // dump z* fp32 to gmem for k_y
    for (int i = tid; i < (128 * NSd) / 4; i += NTH_IT) {
        const int row = (i * 4) >> 9, col = (i * 4) & 511;
        __half2 p0 = *(__half2*)&smh[row * Z_LDH + col];
        __half2 p1 = *(__half2*)&smh[row * Z_LDH + col + 2];
        *(float4*)&g_zf[(size_t)(m0 + row) * NSd + col] =
            make_float4(__low2float(p0), __high2float(p0),
                        __low2float(p1), __high2float(p1));
    }

    // g-phase: g = v * (1 - tanh(xA + z* @ Bm^T)^2); g overwrites z in smem
    mma_pass<NCHUNK>(zb, Z_LDH * 2, g_BmH, NSd, bb, acc);
#pragma unroll
    for (int f = 0; f < 4; ++f) {
#pragma unroll
        for (int g = 0; g < 4; ++g) {
            const int n = wc * 32 + g * 8 + tg * 2;
#pragma unroll
            for (int hr = 0; hr < 2; ++hr) {
                const int off = (f * 16 + hr * 8) * NSd + n;
                float2 xa = *(const float2*)&xaRow[off];
                float2 vv = *(const float2*)&vRow[off];
                float th;
                th = tanh_ap(xa.x + acc[f][g][hr * 2 + 0]);
                __half gx = __float2half_rn(vv.x * (1.f - th * th));
                th = tanh_ap(xa.y + acc[f][g][hr * 2 + 1]);
                __half gy = __float2half_rn(vv.y * (1.f - th * th));
                __half2 hh = __halves2half2(gx, gy);
                stash[(f * 4 + g) * 2 + hr] = *reinterpret_cast<uint32_t*>(&hh);
            }
        }
    }
    mma_pass<NCHUNK>(zb, Z_LDH * 2, g_BmH + (size_t)256 * NSd, NSd, bb, acc);
    __syncthreads();
#pragma unroll
    for (int f = 0; f < 4; ++f) {
#pragma unroll
        for (int g = 0; g < 4; ++g) {
            const int n = wc * 32 + g * 8 + tg * 2;
#pragma unroll
            for (int hr = 0; hr < 2; ++hr) {
                const int ml = mbase + f * 16 + hr * 8;
                const int n2 = 256 + n;
                const int off = (f * 16 + hr * 8) * NSd + n2;
                float2 xa = *(const float2*)&xaRow[off];
                float2 vv = *(const float2*)&vRow[off];
                float th;
                th = tanh_ap(xa.x + acc[f][g][hr * 2 + 0]);
                __half gx = __float2half_rn(vv.x * (1.f - th * th));
                th = tanh_ap(xa.y + acc[f][g][hr * 2 + 1]);
                __half gy = __float2half_rn(vv.y * (1.f - th * th));
                *(__half2*)&smh[ml * Z_LDH + n2] = __halves2half2(gx, gy);
                *(__half2*)&smh[ml * Z_LDH + n] =
                    *reinterpret_cast<__half2*>(&stash[(f * 4 + g) * 2 + hr]);
            }
        }
    }

    // vjp: vJ = g @ Bm ; sum of squares
    float ls = 0.f;
    mma_pass<NCHUNK>(zb, Z_LDH * 2, g_BmTH, NSd, bb, acc);
#pragma unroll
    for (int f = 0; f < 4; ++f)
#pragma unroll
        for (int g = 0; g < 4; ++g)
#pragma unroll
            for (int r = 0; r < 4; ++r) ls += acc[f][g][r] * acc[f][g][r];
    mma_pass<NCHUNK>(zb, Z_LDH * 2, g_BmTH + (size_t)256 * NSd, NSd, bb, acc);
#pragma unroll
    for (int f = 0; f < 4; ++f)
#pragma unroll
        for (int g = 0; g < 4; ++g)
#pragma unroll
            for (int r = 0; r < 4; ++r) ls += acc[f][g][r] * acc[f][g][r];

    float2 bs = block_reduce2(ls, 0.f);
    if (tid == 0) g_jacpart[blockIdx.x] = bs.x;
}

// y = z* @ Wh^T + bh (exact fp32); CTA 0 also finalizes jac_loss.
__global__ void __launch_bounds__(NTHREADS) k_y(const float* __restrict__ Wh,
                                                const float* __restrict__ bh,
                                                float* __restrict__ out) {
    __shared__ float sA[2 * BK * BM];
    __shared__ float sB[2 * BK * BN];
    const int m0 = blockIdx.x * BM;
    ull acc[8][2];
#pragma unroll
    for (int i = 0; i < 8; ++i) { acc[i][0] = 0ull; acc[i][1] = 0ull; }
    gemm_tile_bt(g_zf, NSd, Wh, NSd, m0, 0, NSd, acc, sA, sB);
    const int tid = threadIdx.x;
    const int r0 = (tid >> 4) * 8, c0 = (tid & 15) * 4;
    const float b0 = bh[c0], b1 = bh[c0 + 1], b2 = bh[c0 + 2], b3 = bh[c0 + 3];
#pragma unroll
    for (int r = 0; r < 8; ++r) {
        float2 lo = unpack2(acc[r][0]), hi = unpack2(acc[r][1]);
        float4 o = make_float4(lo.x + b0, lo.y + b1, hi.x + b2, hi.y + b3);
        *(float4*)&out[(size_t)(m0 + r0 + r) * NOUT + c0] = o;
    }

    if (blockIdx.x == 0) {
        __syncthreads();
        float s = (tid < GRID_IT) ? g_jacpart[tid] : 0.f;
        sA[tid] = s; __syncthreads();
#pragma unroll
        for (int o = 128; o > 0; o >>= 1) {
            if (tid < o) sA[tid] += sA[tid + o];
            __syncthreads();
        }
        if (tid == 0) out[(size_t)NM * NOUT] = sA[0] / ((float)NM * (float)NSd);
    }
}

// ---------------- launcher ----------------
extern "C" void kernel_launch(void* const* d_in, const int* in_sizes, int n_in,
                              void* d_out, int out_size) {
    const float* x   = (const float*)d_in[0];
    const float* A   = (const float*)d_in[1];
    const float* Bm  = (const float*)d_in[2];
    const float* b   = (const float*)d_in[3];
    const float* Wh  = (const float*)d_in[4];
    const float* bh  = (const float*)d_in[5];
    const float* v   = (const float*)d_in[6];
    float* out = (float*)d_out;

    static int configured = 0;
    if (!configured) {
        cudaFuncSetAttribute(k_iter, cudaFuncAttributeMaxDynamicSharedMemorySize, SMEM_DYN);
        configured = 1;
    }

    k_prep<<<(NM * NIN) / (2 * 256), 256>>>(x, Bm, A);
    k_iter<<<GRID_IT, NTH_IT, SMEM_DYN>>>(b, v);
    k_y<<<TILES_M, NTHREADS>>>(Wh, bh, out);
}